// round 1
// baseline (speedup 1.0000x reference)
#include <cuda_runtime.h>

#define BB 8
#define QQ 2048
#define KS 2048
#define DD 512

#define BM 128
#define BN 128
#define BKT 16

// scratch for qW = query @ W  (8*2048*512 floats = 33.5 MB)
__device__ float g_qW[BB * QQ * DD];

// Generic 128x128 tile SGEMM, 256 threads, 8x8 per thread, k-tile 16,
// register-prefetch software pipeline.
// BT=1: B is stored [N,K] (K contiguous) -> transpose on smem store (NT gemm).
// EPI=1: apply key-mask + scale epilogue (scores kernel).
template<int BT, int EPI>
__launch_bounds__(256)
__global__ void sgemm_kernel(const float* __restrict__ A, long long sA, int lda,
                             const float* __restrict__ Bm, long long sB, int ldb,
                             float* __restrict__ C, long long sC, int ldc,
                             int Ndim, int Kdim,
                             const int* __restrict__ mask, float scale)
{
    __shared__ float As[BKT][BM + 4];
    __shared__ float Bs[BKT][BN + 4];

    const int bz = blockIdx.z;
    const float* Ab = A  + (long long)bz * sA;
    const float* Bb = Bm + (long long)bz * sB;
    float*       Cb = C  + (long long)bz * sC;

    const int row0 = blockIdx.y * BM;
    const int col0 = blockIdx.x * BN;
    const int tid  = threadIdx.x;

    // loader indices
    const int a_row = tid >> 2;          // 0..63 (+64 on second pass)
    const int a_k4  = (tid & 3) << 2;    // 0,4,8,12
    const int b_k   = tid >> 5;          // 0..7 (+8 on second pass)
    const int b_n4  = (tid & 31) << 2;   // 0..124

    const float* aptr = Ab + (long long)(row0 + a_row) * lda + a_k4;
    const float* bptr = BT ? (Bb + (long long)(col0 + a_row) * ldb + a_k4)
                           : (Bb + (long long)b_k * ldb + col0 + b_n4);

    float acc[8][8];
    #pragma unroll
    for (int i = 0; i < 8; i++)
        #pragma unroll
        for (int j = 0; j < 8; j++) acc[i][j] = 0.f;

    const int KT = Kdim / BKT;

    float4 ra[2], rb[2];
    #pragma unroll
    for (int r = 0; r < 2; r++) {
        ra[r] = *(const float4*)(aptr + (long long)(64 * r) * lda);
        rb[r] = BT ? *(const float4*)(bptr + (long long)(64 * r) * ldb)
                   : *(const float4*)(bptr + (long long)(8  * r) * ldb);
    }

    const int ty = tid >> 4, tx = tid & 15;

    for (int kt = 0; kt < KT; ++kt) {
        // regs -> smem
        #pragma unroll
        for (int r = 0; r < 2; r++) {
            const int rr = a_row + 64 * r;
            As[a_k4 + 0][rr] = ra[r].x;
            As[a_k4 + 1][rr] = ra[r].y;
            As[a_k4 + 2][rr] = ra[r].z;
            As[a_k4 + 3][rr] = ra[r].w;
            if (BT) {
                Bs[a_k4 + 0][rr] = rb[r].x;
                Bs[a_k4 + 1][rr] = rb[r].y;
                Bs[a_k4 + 2][rr] = rb[r].z;
                Bs[a_k4 + 3][rr] = rb[r].w;
            } else {
                *(float4*)&Bs[b_k + 8 * r][b_n4] = rb[r];
            }
        }
        __syncthreads();

        // prefetch next k-tile into regs (LDGs fly during the FFMA block)
        if (kt + 1 < KT) {
            const float* ap = aptr + (kt + 1) * BKT;
            #pragma unroll
            for (int r = 0; r < 2; r++)
                ra[r] = *(const float4*)(ap + (long long)(64 * r) * lda);
            if (BT) {
                const float* bp = bptr + (kt + 1) * BKT;
                #pragma unroll
                for (int r = 0; r < 2; r++)
                    rb[r] = *(const float4*)(bp + (long long)(64 * r) * ldb);
            } else {
                const float* bp = bptr + (long long)(kt + 1) * BKT * ldb;
                #pragma unroll
                for (int r = 0; r < 2; r++)
                    rb[r] = *(const float4*)(bp + (long long)(8 * r) * ldb);
            }
        }

        // compute
        #pragma unroll
        for (int kk = 0; kk < BKT; ++kk) {
            float a[8], b[8];
            *(float4*)(a)     = *(const float4*)&As[kk][ty * 8];
            *(float4*)(a + 4) = *(const float4*)&As[kk][ty * 8 + 4];
            *(float4*)(b)     = *(const float4*)&Bs[kk][tx * 8];
            *(float4*)(b + 4) = *(const float4*)&Bs[kk][tx * 8 + 4];
            #pragma unroll
            for (int i = 0; i < 8; i++)
                #pragma unroll
                for (int j = 0; j < 8; j++)
                    acc[i][j] += a[i] * b[j];
        }
        __syncthreads();
    }

    // epilogue
    #pragma unroll
    for (int i = 0; i < 8; i++) {
        const int cm = row0 + ty * 8 + i;
        float* crow = Cb + (long long)cm * ldc + col0 + tx * 8;
        if (EPI == 1) {
            #pragma unroll
            for (int j = 0; j < 8; j++) {
                const int cn = col0 + tx * 8 + j;
                const int mk = mask[(long long)bz * Ndim + cn];
                acc[i][j] = (mk ? acc[i][j] : -1e20f) * scale;
            }
        }
        *(float4*)(crow)     = make_float4(acc[i][0], acc[i][1], acc[i][2], acc[i][3]);
        *(float4*)(crow + 4) = make_float4(acc[i][4], acc[i][5], acc[i][6], acc[i][7]);
    }
}

// Row softmax over dist[B*Q][K], in place. One block (256 thr) per row.
__global__ void softmax_kernel(float* __restrict__ dist)
{
    const long long row = blockIdx.x;
    float* p = dist + row * (long long)KS;
    const int tid = threadIdx.x;

    float4 v0 = ((const float4*)p)[tid];
    float4 v1 = ((const float4*)p)[tid + 256];

    __shared__ float red[8];

    float m = fmaxf(fmaxf(fmaxf(v0.x, v0.y), fmaxf(v0.z, v0.w)),
                    fmaxf(fmaxf(v1.x, v1.y), fmaxf(v1.z, v1.w)));
    #pragma unroll
    for (int o = 16; o > 0; o >>= 1)
        m = fmaxf(m, __shfl_xor_sync(0xffffffffu, m, o));
    if ((tid & 31) == 0) red[tid >> 5] = m;
    __syncthreads();
    m = red[0];
    #pragma unroll
    for (int i = 1; i < 8; i++) m = fmaxf(m, red[i]);
    __syncthreads();

    v0.x = __expf(v0.x - m); v0.y = __expf(v0.y - m);
    v0.z = __expf(v0.z - m); v0.w = __expf(v0.w - m);
    v1.x = __expf(v1.x - m); v1.y = __expf(v1.y - m);
    v1.z = __expf(v1.z - m); v1.w = __expf(v1.w - m);

    float s = v0.x + v0.y + v0.z + v0.w + v1.x + v1.y + v1.z + v1.w;
    #pragma unroll
    for (int o = 16; o > 0; o >>= 1)
        s += __shfl_xor_sync(0xffffffffu, s, o);
    if ((tid & 31) == 0) red[tid >> 5] = s;
    __syncthreads();
    float tot = red[0];
    #pragma unroll
    for (int i = 1; i < 8; i++) tot += red[i];

    const float inv = 1.0f / tot;
    v0.x *= inv; v0.y *= inv; v0.z *= inv; v0.w *= inv;
    v1.x *= inv; v1.y *= inv; v1.z *= inv; v1.w *= inv;

    ((float4*)p)[tid]       = v0;
    ((float4*)p)[tid + 256] = v1;
}

static float* get_qW_ptr()
{
    static float* p = nullptr;
    if (!p) cudaGetSymbolAddress((void**)&p, g_qW);
    return p;
}

extern "C" void kernel_launch(void* const* d_in, const int* in_sizes, int n_in,
                              void* d_out, int out_size)
{
    const float* query = (const float*)d_in[0];
    const float* key   = (const float*)d_in[1];
    const float* value = (const float*)d_in[2];
    const int*   mask  = (const int*)d_in[3];
    const float* W     = (const float*)d_in[4];

    float* ctx  = (float*)d_out;                          // [B,Q,D]
    float* dist = ctx + (long long)BB * QQ * DD;          // [B,Q,K]
    float* qW   = get_qW_ptr();

    const float scale = 0.044194173824159216f;            // 1/sqrt(512)

    // 1) qW = query @ W   (M=16384, N=512, K=512)
    sgemm_kernel<0, 0><<<dim3(DD / BN, (BB * QQ) / BM, 1), 256>>>(
        query, 0, DD, W, 0, DD, qW, 0, DD, DD, DD, nullptr, 0.f);

    // 2) scores = qW @ key^T, mask + scale -> dist region (per batch, NT gemm)
    sgemm_kernel<1, 1><<<dim3(KS / BN, QQ / BM, BB), 256>>>(
        qW, (long long)QQ * DD, DD, key, (long long)KS * DD, DD,
        dist, (long long)QQ * KS, KS, KS, DD, mask, scale);

    // 3) softmax rows in place
    softmax_kernel<<<BB * QQ, 256>>>(dist);

    // 4) context = dist @ value  (per batch, NN gemm, K=2048)
    sgemm_kernel<0, 0><<<dim3(DD / BN, QQ / BM, BB), 256>>>(
        dist, (long long)QQ * KS, KS, value, (long long)KS * DD, DD,
        ctx, (long long)QQ * DD, DD, DD, KS, nullptr, 0.f);
}

// round 3
// speedup vs baseline: 2.1378x; 2.1378x over previous
#include <cuda_runtime.h>
#include <cuda_bf16.h>
#include <cstdint>

#define BB   8
#define QQ   2048
#define KSEQ 2048
#define DIM  512

// ---------------- device scratch: bf16 split planes (hi, lo) ----------------
__device__ __align__(1024) __nv_bfloat16 g_qsp [2u*16384u*512u];   // query
__device__ __align__(1024) __nv_bfloat16 g_wtsp[2u*512u*512u];     // W^T
__device__ __align__(1024) __nv_bfloat16 g_ksp [2u*16384u*512u];   // key
__device__ __align__(1024) __nv_bfloat16 g_qwsp[2u*16384u*512u];   // qW
__device__ __align__(1024) __nv_bfloat16 g_vtsp[2u*4096u*2048u];   // value^T per batch
__device__ __align__(1024) __nv_bfloat16 g_dssp[2u*16384u*2048u];  // dist

__device__ __forceinline__ uint32_t smem_u32(const void* p) {
    uint32_t a;
    asm("{ .reg .u64 t; cvta.to.shared.u64 t, %1; cvt.u32.u64 %0, t; }"
        : "=r"(a) : "l"(p));
    return a;
}
__device__ __forceinline__ void cp16(uint32_t dst, const void* src) {
    asm volatile("cp.async.cg.shared.global [%0], [%1], 16;"
                 :: "r"(dst), "l"(src) : "memory");
}
__device__ __forceinline__ void cp_commit() {
    asm volatile("cp.async.commit_group;" ::: "memory");
}
__device__ __forceinline__ void cp_wait1() {
    asm volatile("cp.async.wait_group 1;" ::: "memory");
}
__device__ __forceinline__ void ldmx4(uint32_t r[4], uint32_t addr) {
    asm volatile("ldmatrix.sync.aligned.m8n8.x4.shared.b16 {%0,%1,%2,%3}, [%4];"
                 : "=r"(r[0]), "=r"(r[1]), "=r"(r[2]), "=r"(r[3]) : "r"(addr));
}
__device__ __forceinline__ void mma16816(float c[4], const uint32_t a[4], const uint32_t* b) {
    asm volatile("mma.sync.aligned.m16n8k16.row.col.f32.bf16.bf16.f32 "
                 "{%0,%1,%2,%3}, {%4,%5,%6,%7}, {%8,%9}, {%0,%1,%2,%3};"
                 : "+f"(c[0]), "+f"(c[1]), "+f"(c[2]), "+f"(c[3])
                 : "r"(a[0]), "r"(a[1]), "r"(a[2]), "r"(a[3]), "r"(b[0]), "r"(b[1]));
}
__device__ __forceinline__ void splitf(float v, __nv_bfloat16& h, __nv_bfloat16& l) {
    h = __float2bfloat16(v);
    l = __float2bfloat16(v - __bfloat162float(h));
}

// ---------------- bf16x3 mma.sync GEMM --------------------------------------
// C[M,N] = A[M,K] @ B[N,K]^T  (both row-major, K contiguous), hi/lo planes.
// CTA tile 128x128, BK=32, 3-stage cp.async pipeline, 8 warps (2M x 4N).
// smem tile rows padded 64B->80B: conflict-free ldmatrix.
#define TILEB 10240            // 128 rows * 80B
#define STGB  (4 * TILEB)      // Ah, Al, Bh, Bl
#define NSTG  3
#define SMEM_DYN (NSTG * STGB)

// EPI: 0 = bf16-split out (qW), 1 = mask+scale fp32 (scores), 2 = fp32 (ctx)
template <int EPI>
__global__ __launch_bounds__(256, 1) void mma_gemm(
    const __nv_bfloat16* __restrict__ A, long long Aplane, int lda, int a_bs,
    const __nv_bfloat16* __restrict__ B, long long Bplane, int ldb, int b_bs,
    int nch,
    float* __restrict__ outF,
    __nv_bfloat16* __restrict__ outH, long long hplane,
    const int* __restrict__ mask, float scale,
    int ldc, long long out_bstride)
{
    extern __shared__ char smem[];
    const uint32_t sb = smem_u32(smem);

    const int tid = threadIdx.x;
    const int lane = tid & 31, wrp = tid >> 5;
    const int wm = (wrp >> 2) * 64, wn = (wrp & 3) * 32;
    const int bz = blockIdx.z;
    const int arow = a_bs * bz + blockIdx.y * 128;
    const int brow = b_bs * bz + blockIdx.x * 128;

    const __nv_bfloat16* Ag = A + (long long)arow * lda;
    const __nv_bfloat16* Bg = B + (long long)brow * ldb;

    // loader: 2048 16B chunks/stage (4 tiles x 128 rows x 4), 8 per thread
    const int r0 = tid >> 2, c0 = (tid & 3) * 8;          // chunk 0 of this thread
    // per-tile source row pointers for chunks {tid, tid+256}: rows r0, r0+64

    // fragment smem offsets (per thread, constant)
    const int g = lane >> 3, lr = lane & 7;
    const uint32_t aoff = (uint32_t)(wm + (g & 1) * 8 + lr) * 80 + ((g >> 1) * 16);
    const uint32_t boff = (uint32_t)(wn + ((g >> 1) & 1) * 8 + lr) * 80 + ((g & 1) * 16);

    float acc[4][4][4];
    #pragma unroll
    for (int mt = 0; mt < 4; mt++)
        #pragma unroll
        for (int nt = 0; nt < 4; nt++)
            #pragma unroll
            for (int i = 0; i < 4; i++) acc[mt][nt][i] = 0.f;

    auto load_stage = [&](int buf, int k0) {
        const uint32_t st = sb + buf * STGB;
        #pragma unroll
        for (int h = 0; h < 2; h++) {
            const int r = r0 + h * 64;
            const uint32_t doff = (uint32_t)r * 80 + (c0 * 2);
            const __nv_bfloat16* a_src = Ag + (long long)r * lda + k0 + c0;
            const __nv_bfloat16* b_src = Bg + (long long)r * ldb + k0 + c0;
            cp16(st + doff,             a_src);
            cp16(st + TILEB + doff,     a_src + Aplane);
            cp16(st + 2 * TILEB + doff, b_src);
            cp16(st + 3 * TILEB + doff, b_src + Bplane);
        }
        cp_commit();
    };

    load_stage(0, 0);
    load_stage(1, 32);

    for (int kt = 0; kt < nch; ++kt) {
        cp_wait1();
        __syncthreads();
        if (kt + 2 < nch) load_stage((kt + 2) % NSTG, (kt + 2) * 32);

        const uint32_t st = sb + (kt % NSTG) * STGB;
        #pragma unroll
        for (int kk = 0; kk < 2; kk++) {
            uint32_t ah[4][4], al[4][4], bh[2][4], bl[2][4];
            #pragma unroll
            for (int mt = 0; mt < 4; mt++) {
                const uint32_t ad = st + mt * (16 * 80) + kk * 32 + aoff;
                ldmx4(ah[mt], ad);
                ldmx4(al[mt], ad + TILEB);
            }
            #pragma unroll
            for (int nt2 = 0; nt2 < 2; nt2++) {
                const uint32_t bd = st + 2 * TILEB + nt2 * (16 * 80) + kk * 32 + boff;
                ldmx4(bh[nt2], bd);
                ldmx4(bl[nt2], bd + TILEB);
            }
            #pragma unroll
            for (int mt = 0; mt < 4; mt++)
                #pragma unroll
                for (int nt = 0; nt < 4; nt++) {
                    const uint32_t* ph = &bh[nt >> 1][(nt & 1) * 2];
                    const uint32_t* pl = &bl[nt >> 1][(nt & 1) * 2];
                    mma16816(acc[mt][nt], ah[mt], ph);
                    mma16816(acc[mt][nt], al[mt], ph);
                    mma16816(acc[mt][nt], ah[mt], pl);
                }
        }
    }

    // ---- epilogue ----
    const int rbase = blockIdx.y * 128 + wm + (lane >> 2);
    const int cbase = blockIdx.x * 128 + wn + ((lane & 3) << 1);

    #pragma unroll
    for (int mt = 0; mt < 4; mt++) {
        #pragma unroll
        for (int nt = 0; nt < 4; nt++) {
            const int col = cbase + nt * 8;
            #pragma unroll
            for (int h = 0; h < 2; h++) {
                const int row = rbase + mt * 16 + h * 8;
                float v0 = acc[mt][nt][2 * h], v1 = acc[mt][nt][2 * h + 1];
                if (EPI == 0) {
                    const long long o = (long long)row * ldc + col;
                    __nv_bfloat16 h0, l0, h1, l1;
                    splitf(v0, h0, l0); splitf(v1, h1, l1);
                    *(__nv_bfloat162*)(outH + o)          = __halves2bfloat162(h0, h1);
                    *(__nv_bfloat162*)(outH + hplane + o) = __halves2bfloat162(l0, l1);
                } else if (EPI == 1) {
                    const int* mrow = mask + bz * KSEQ;
                    v0 = (mrow[col] ? v0 : -1e20f) * scale;
                    v1 = (mrow[col + 1] ? v1 : -1e20f) * scale;
                    const long long o = (long long)bz * out_bstride + (long long)row * ldc + col;
                    *(float2*)(outF + o) = make_float2(v0, v1);
                } else {
                    const long long o = (long long)bz * out_bstride + (long long)row * ldc + col;
                    *(float2*)(outF + o) = make_float2(v0, v1);
                }
            }
        }
    }
}

// ---------------- pre/post elementwise kernels ------------------------------
__global__ void split_kernel(const float* __restrict__ in, __nv_bfloat16* __restrict__ out,
                             long long plane)
{
    const long long i = ((long long)blockIdx.x * blockDim.x + threadIdx.x) * 4;
    float4 v = *(const float4*)(in + i);
    __nv_bfloat16 h0, l0, h1, l1, h2, l2, h3, l3;
    splitf(v.x, h0, l0); splitf(v.y, h1, l1); splitf(v.z, h2, l2); splitf(v.w, h3, l3);
    *(__nv_bfloat162*)(out + i)             = __halves2bfloat162(h0, h1);
    *(__nv_bfloat162*)(out + i + 2)         = __halves2bfloat162(h2, h3);
    *(__nv_bfloat162*)(out + plane + i)     = __halves2bfloat162(l0, l1);
    *(__nv_bfloat162*)(out + plane + i + 2) = __halves2bfloat162(l2, l3);
}

// transpose [R,C] -> [C,R] per batch, bf16-split output
__global__ void tsplit_kernel(const float* __restrict__ in, __nv_bfloat16* __restrict__ out,
                              int R, int C, long long plane)
{
    __shared__ float t[32][33];
    const int bz = blockIdx.z;
    const long long boff = (long long)bz * R * C;
    const int x = blockIdx.x * 32 + threadIdx.x;
    #pragma unroll
    for (int i = 0; i < 4; ++i) {
        const int y = blockIdx.y * 32 + threadIdx.y + i * 8;
        t[threadIdx.y + i * 8][threadIdx.x] = in[boff + (long long)y * C + x];
    }
    __syncthreads();
    const int xo = blockIdx.y * 32 + threadIdx.x;
    #pragma unroll
    for (int i = 0; i < 4; ++i) {
        const int yo = blockIdx.x * 32 + threadIdx.y + i * 8;
        const float v = t[threadIdx.x][threadIdx.y + i * 8];
        __nv_bfloat16 h, l; splitf(v, h, l);
        const long long o = boff + (long long)yo * R + xo;
        out[o] = h;
        out[plane + o] = l;
    }
}

// row softmax over dist[16384][2048] in place + bf16 split planes
__global__ void softmax_split_kernel(float* __restrict__ dist,
                                     __nv_bfloat16* __restrict__ ds, long long plane)
{
    const long long row = blockIdx.x;
    float* p = dist + row * (long long)KSEQ;
    const int tid = threadIdx.x;

    float4 v0 = ((const float4*)p)[tid];
    float4 v1 = ((const float4*)p)[tid + 256];

    __shared__ float red[8];
    float m = fmaxf(fmaxf(fmaxf(v0.x, v0.y), fmaxf(v0.z, v0.w)),
                    fmaxf(fmaxf(v1.x, v1.y), fmaxf(v1.z, v1.w)));
    #pragma unroll
    for (int o = 16; o > 0; o >>= 1) m = fmaxf(m, __shfl_xor_sync(0xffffffffu, m, o));
    if ((tid & 31) == 0) red[tid >> 5] = m;
    __syncthreads();
    m = red[0];
    #pragma unroll
    for (int i = 1; i < 8; i++) m = fmaxf(m, red[i]);
    __syncthreads();

    v0.x = __expf(v0.x - m); v0.y = __expf(v0.y - m);
    v0.z = __expf(v0.z - m); v0.w = __expf(v0.w - m);
    v1.x = __expf(v1.x - m); v1.y = __expf(v1.y - m);
    v1.z = __expf(v1.z - m); v1.w = __expf(v1.w - m);

    float s = v0.x + v0.y + v0.z + v0.w + v1.x + v1.y + v1.z + v1.w;
    #pragma unroll
    for (int o = 16; o > 0; o >>= 1) s += __shfl_xor_sync(0xffffffffu, s, o);
    if ((tid & 31) == 0) red[tid >> 5] = s;
    __syncthreads();
    float tot = red[0];
    #pragma unroll
    for (int i = 1; i < 8; i++) tot += red[i];

    const float inv = 1.0f / tot;
    v0.x *= inv; v0.y *= inv; v0.z *= inv; v0.w *= inv;
    v1.x *= inv; v1.y *= inv; v1.z *= inv; v1.w *= inv;

    ((float4*)p)[tid]       = v0;
    ((float4*)p)[tid + 256] = v1;

    const long long b0 = row * KSEQ + tid * 4;
    const long long b1 = b0 + 1024;
    __nv_bfloat16 h0, l0, h1, l1;
    splitf(v0.x, h0, l0); splitf(v0.y, h1, l1);
    *(__nv_bfloat162*)(ds + b0)         = __halves2bfloat162(h0, h1);
    *(__nv_bfloat162*)(ds + plane + b0) = __halves2bfloat162(l0, l1);
    splitf(v0.z, h0, l0); splitf(v0.w, h1, l1);
    *(__nv_bfloat162*)(ds + b0 + 2)         = __halves2bfloat162(h0, h1);
    *(__nv_bfloat162*)(ds + plane + b0 + 2) = __halves2bfloat162(l0, l1);
    splitf(v1.x, h0, l0); splitf(v1.y, h1, l1);
    *(__nv_bfloat162*)(ds + b1)         = __halves2bfloat162(h0, h1);
    *(__nv_bfloat162*)(ds + plane + b1) = __halves2bfloat162(l0, l1);
    splitf(v1.z, h0, l0); splitf(v1.w, h1, l1);
    *(__nv_bfloat162*)(ds + b1 + 2)         = __halves2bfloat162(h0, h1);
    *(__nv_bfloat162*)(ds + plane + b1 + 2) = __halves2bfloat162(l0, l1);
}

// ---------------- host side -------------------------------------------------
struct Scratch { __nv_bfloat16 *q, *wt, *k, *qw, *vt, *ds; };
static Scratch get_scratch()
{
    static Scratch s = { nullptr, nullptr, nullptr, nullptr, nullptr, nullptr };
    if (!s.q) {
        cudaGetSymbolAddress((void**)&s.q,  g_qsp);
        cudaGetSymbolAddress((void**)&s.wt, g_wtsp);
        cudaGetSymbolAddress((void**)&s.k,  g_ksp);
        cudaGetSymbolAddress((void**)&s.qw, g_qwsp);
        cudaGetSymbolAddress((void**)&s.vt, g_vtsp);
        cudaGetSymbolAddress((void**)&s.ds, g_dssp);
    }
    return s;
}

extern "C" void kernel_launch(void* const* d_in, const int* in_sizes, int n_in,
                              void* d_out, int out_size)
{
    const float* query = (const float*)d_in[0];
    const float* key   = (const float*)d_in[1];
    const float* value = (const float*)d_in[2];
    const int*   mask  = (const int*)d_in[3];
    const float* W     = (const float*)d_in[4];

    float* ctx  = (float*)d_out;                               // [B,Q,D]
    float* dist = ctx + (long long)BB * QQ * DIM;              // [B,Q,K]

    Scratch sc = get_scratch();
    const float scale = 0.044194173824159216f;                 // 1/sqrt(512)

    static bool attr_done = false;
    if (!attr_done) {
        cudaFuncSetAttribute(mma_gemm<0>, cudaFuncAttributeMaxDynamicSharedMemorySize, SMEM_DYN);
        cudaFuncSetAttribute(mma_gemm<1>, cudaFuncAttributeMaxDynamicSharedMemorySize, SMEM_DYN);
        cudaFuncSetAttribute(mma_gemm<2>, cudaFuncAttributeMaxDynamicSharedMemorySize, SMEM_DYN);
        attr_done = true;
    }

    const long long PQ = (long long)16384 * 512;   // q/k/qw plane elems
    const long long PV = (long long)4096 * 2048;   // vt plane
    const long long PD = (long long)16384 * 2048;  // dist plane
    const long long PW = (long long)512 * 512;     // wt plane

    // 1) splits / transposes
    split_kernel<<<8192, 256>>>(query, sc.q, PQ);
    split_kernel<<<8192, 256>>>(key,   sc.k, PQ);
    tsplit_kernel<<<dim3(16, 64, 8), dim3(32, 8)>>>(value, sc.vt, 2048, 512, PV);
    tsplit_kernel<<<dim3(16, 16, 1), dim3(32, 8)>>>(W,     sc.wt, 512,  512, PW);

    // 2) qW = q @ (W^T)^T -> bf16 split planes   (M=16384, N=512, K=512)
    mma_gemm<0><<<dim3(4, 128, 1), 256, SMEM_DYN>>>(
        sc.q, PQ, 512, 0, sc.wt, PW, 512, 0, 16,
        nullptr, sc.qw, PQ, nullptr, 0.f, 512, 0);

    // 3) scores = qW @ key^T, mask+scale -> dist fp32  (per batch 2048x2048, K=512)
    mma_gemm<1><<<dim3(16, 16, 8), 256, SMEM_DYN>>>(
        sc.qw, PQ, 512, 2048, sc.k, PQ, 512, 2048, 16,
        dist, nullptr, 0, mask, scale, 2048, (long long)2048 * 2048);

    // 4) softmax rows in place + bf16 split of dist
    softmax_split_kernel<<<16384, 256>>>(dist, sc.ds, PD);

    // 5) context = dist @ (v^T)^T -> fp32  (per batch 2048x512, K=2048)
    mma_gemm<2><<<dim3(4, 16, 8), 256, SMEM_DYN>>>(
        sc.ds, PD, 2048, 2048, sc.vt, PV, 2048, 512, 64,
        ctx, nullptr, 0, nullptr, 0.f, 512, (long long)2048 * 512);
}

// round 5
// speedup vs baseline: 2.5198x; 1.1787x over previous
#include <cuda_runtime.h>
#include <cuda_bf16.h>
#include <cstdint>

#define BB   8
#define QQ   2048
#define KSEQ 2048
#define DIM  512

// ---------------- device scratch: bf16 split planes (hi, lo) ----------------
__device__ __align__(1024) __nv_bfloat16 g_qsp [2u*16384u*512u];   // query
__device__ __align__(1024) __nv_bfloat16 g_wtsp[2u*512u*512u];     // W^T
__device__ __align__(1024) __nv_bfloat16 g_ksp [2u*16384u*512u];   // key
__device__ __align__(1024) __nv_bfloat16 g_qwsp[2u*16384u*512u];   // qW
__device__ __align__(1024) __nv_bfloat16 g_vtsp[2u*4096u*2048u];   // value^T per batch
__device__ __align__(1024) __nv_bfloat16 g_dssp[2u*16384u*2048u];  // dist

__device__ __forceinline__ uint32_t smem_u32(const void* p) {
    uint32_t a;
    asm("{ .reg .u64 t; cvta.to.shared.u64 t, %1; cvt.u32.u64 %0, t; }"
        : "=r"(a) : "l"(p));
    return a;
}
__device__ __forceinline__ void cp16(uint32_t dst, const void* src) {
    asm volatile("cp.async.cg.shared.global [%0], [%1], 16;"
                 :: "r"(dst), "l"(src) : "memory");
}
__device__ __forceinline__ void cp_commit() {
    asm volatile("cp.async.commit_group;" ::: "memory");
}
__device__ __forceinline__ void cp_wait1() {
    asm volatile("cp.async.wait_group 1;" ::: "memory");
}
__device__ __forceinline__ void cp_wait0() {
    asm volatile("cp.async.wait_group 0;" ::: "memory");
}
__device__ __forceinline__ void ldmx4(uint32_t r[4], uint32_t addr) {
    asm volatile("ldmatrix.sync.aligned.m8n8.x4.shared.b16 {%0,%1,%2,%3}, [%4];"
                 : "=r"(r[0]), "=r"(r[1]), "=r"(r[2]), "=r"(r[3]) : "r"(addr));
}
__device__ __forceinline__ void mma16816(float c[4], const uint32_t a[4], const uint32_t* b) {
    asm volatile("mma.sync.aligned.m16n8k16.row.col.f32.bf16.bf16.f32 "
                 "{%0,%1,%2,%3}, {%4,%5,%6,%7}, {%8,%9}, {%0,%1,%2,%3};"
                 : "+f"(c[0]), "+f"(c[1]), "+f"(c[2]), "+f"(c[3])
                 : "r"(a[0]), "r"(a[1]), "r"(a[2]), "r"(a[3]), "r"(b[0]), "r"(b[1]));
}
__device__ __forceinline__ void splitf(float v, __nv_bfloat16& h, __nv_bfloat16& l) {
    h = __float2bfloat16(v);
    l = __float2bfloat16(v - __bfloat162float(h));
}

// ---------------- bf16x3 mma.sync GEMM --------------------------------------
// C[M,N] = A[M,K] @ B[N,K]^T (row-major, K contiguous), hi/lo planes.
// CTA tile 128x128, BK=32, 2-stage cp.async pipeline, 8 warps, 2 CTAs/SM.
#define TILEB 10240            // 128 rows * 80B (conflict-free ldmatrix)
#define STGB  (4 * TILEB)      // Ah, Al, Bh, Bl
#define NSTG  2
#define SMEM_DYN (NSTG * STGB)

// EPI: 0 = bf16-split out (qW), 1 = mask+scale fp32 (scores), 2 = fp32 (ctx)
template <int EPI>
__global__ __launch_bounds__(256, 2) void mma_gemm(
    const __nv_bfloat16* __restrict__ A, long long Aplane, int lda,
    const __nv_bfloat16* __restrict__ B, long long Bplane, int ldb,
    int nch,
    float* __restrict__ outF,
    __nv_bfloat16* __restrict__ outH, long long hplane,
    const int* __restrict__ mask, float scale, int ldc)
{
    extern __shared__ char smem[];
    const uint32_t sb = smem_u32(smem);

    const int tid = threadIdx.x;
    const int lane = tid & 31, wrp = tid >> 5;
    const int wm = (wrp >> 2) * 64, wn = (wrp & 3) * 32;

    const __nv_bfloat16* Ag = A + (long long)(blockIdx.y * 128) * lda;
    const __nv_bfloat16* Bg = B + (long long)(blockIdx.x * 128) * ldb;

    const int r0 = tid >> 2, c0 = (tid & 3) * 8;

    const int g = lane >> 3, lr = lane & 7;
    const uint32_t aoff = (uint32_t)(wm + (g & 1) * 8 + lr) * 80 + ((g >> 1) * 16);
    const uint32_t boff = (uint32_t)(wn + ((g >> 1) & 1) * 8 + lr) * 80 + ((g & 1) * 16);

    float acc[4][4][4];
    #pragma unroll
    for (int mt = 0; mt < 4; mt++)
        #pragma unroll
        for (int nt = 0; nt < 4; nt++)
            #pragma unroll
            for (int i = 0; i < 4; i++) acc[mt][nt][i] = 0.f;

    auto load_stage = [&](int buf, int k0) {
        const uint32_t st = sb + buf * STGB;
        #pragma unroll
        for (int h = 0; h < 2; h++) {
            const int r = r0 + h * 64;
            const uint32_t doff = (uint32_t)r * 80 + (c0 * 2);
            const __nv_bfloat16* a_src = Ag + (long long)r * lda + k0 + c0;
            const __nv_bfloat16* b_src = Bg + (long long)r * ldb + k0 + c0;
            cp16(st + doff,             a_src);
            cp16(st + TILEB + doff,     a_src + Aplane);
            cp16(st + 2 * TILEB + doff, b_src);
            cp16(st + 3 * TILEB + doff, b_src + Bplane);
        }
        cp_commit();
    };

    load_stage(0, 0);
    load_stage(1, 32);

    for (int kt = 0; kt < nch; ++kt) {
        // Tail-safe wait: for the last chunk no newer group exists, so
        // wait_group 1 would let OUR chunk's cp.async still be in flight.
        if (kt + 1 < nch) cp_wait1(); else cp_wait0();
        __syncthreads();

        const uint32_t st = sb + (kt & 1) * STGB;
        #pragma unroll
        for (int kk = 0; kk < 2; kk++) {
            uint32_t ah[4][4], al[4][4], bh[2][4], bl[2][4];
            #pragma unroll
            for (int mt = 0; mt < 4; mt++) {
                const uint32_t ad = st + mt * (16 * 80) + kk * 32 + aoff;
                ldmx4(ah[mt], ad);
                ldmx4(al[mt], ad + TILEB);
            }
            #pragma unroll
            for (int nt2 = 0; nt2 < 2; nt2++) {
                const uint32_t bd = st + 2 * TILEB + nt2 * (16 * 80) + kk * 32 + boff;
                ldmx4(bh[nt2], bd);
                ldmx4(bl[nt2], bd + TILEB);
            }
            #pragma unroll
            for (int mt = 0; mt < 4; mt++)
                #pragma unroll
                for (int nt = 0; nt < 4; nt++) {
                    const uint32_t* ph = &bh[nt >> 1][(nt & 1) * 2];
                    const uint32_t* pl = &bl[nt >> 1][(nt & 1) * 2];
                    mma16816(acc[mt][nt], ah[mt], ph);
                    mma16816(acc[mt][nt], al[mt], ph);
                    mma16816(acc[mt][nt], ah[mt], pl);
                }
        }
        __syncthreads();
        if (kt + 2 < nch) load_stage(kt & 1, (kt + 2) * 32);
    }

    // ---- epilogue ----
    const int rbase = blockIdx.y * 128 + wm + (lane >> 2);
    const int cbase = blockIdx.x * 128 + wn + ((lane & 3) << 1);

    #pragma unroll
    for (int mt = 0; mt < 4; mt++) {
        #pragma unroll
        for (int nt = 0; nt < 4; nt++) {
            const int col = cbase + nt * 8;
            #pragma unroll
            for (int h = 0; h < 2; h++) {
                const int row = rbase + mt * 16 + h * 8;
                float v0 = acc[mt][nt][2 * h], v1 = acc[mt][nt][2 * h + 1];
                if (EPI == 0) {
                    const long long o = (long long)row * ldc + col;
                    __nv_bfloat16 h0, l0, h1, l1;
                    splitf(v0, h0, l0); splitf(v1, h1, l1);
                    *(__nv_bfloat162*)(outH + o)          = __halves2bfloat162(h0, h1);
                    *(__nv_bfloat162*)(outH + hplane + o) = __halves2bfloat162(l0, l1);
                } else if (EPI == 1) {
                    v0 = (mask[col] ? v0 : -1e20f) * scale;
                    v1 = (mask[col + 1] ? v1 : -1e20f) * scale;
                    const long long o = (long long)row * ldc + col;
                    *(float2*)(outF + o) = make_float2(v0, v1);
                } else {
                    const long long o = (long long)row * ldc + col;
                    *(float2*)(outF + o) = make_float2(v0, v1);
                }
            }
        }
    }
}

// ---------------- pre/post elementwise kernels ------------------------------
__global__ void split_kernel(const float* __restrict__ in, __nv_bfloat16* __restrict__ out,
                             long long plane)
{
    const long long i = ((long long)blockIdx.x * blockDim.x + threadIdx.x) * 4;
    float4 v = *(const float4*)(in + i);
    __nv_bfloat16 h0, l0, h1, l1, h2, l2, h3, l3;
    splitf(v.x, h0, l0); splitf(v.y, h1, l1); splitf(v.z, h2, l2); splitf(v.w, h3, l3);
    *(__nv_bfloat162*)(out + i)             = __halves2bfloat162(h0, h1);
    *(__nv_bfloat162*)(out + i + 2)         = __halves2bfloat162(h2, h3);
    *(__nv_bfloat162*)(out + plane + i)     = __halves2bfloat162(l0, l1);
    *(__nv_bfloat162*)(out + plane + i + 2) = __halves2bfloat162(l2, l3);
}

// transpose [R,C] -> [C,R] per batch, bf16-split output
__global__ void tsplit_kernel(const float* __restrict__ in, __nv_bfloat16* __restrict__ out,
                              int R, int C, long long plane)
{
    __shared__ float t[32][33];
    const int bz = blockIdx.z;
    const long long boff = (long long)bz * R * C;
    const int x = blockIdx.x * 32 + threadIdx.x;
    #pragma unroll
    for (int i = 0; i < 4; ++i) {
        const int y = blockIdx.y * 32 + threadIdx.y + i * 8;
        t[threadIdx.y + i * 8][threadIdx.x] = in[boff + (long long)y * C + x];
    }
    __syncthreads();
    const int xo = blockIdx.y * 32 + threadIdx.x;
    #pragma unroll
    for (int i = 0; i < 4; ++i) {
        const int yo = blockIdx.x * 32 + threadIdx.y + i * 8;
        const float v = t[threadIdx.x][threadIdx.y + i * 8];
        __nv_bfloat16 h, l; splitf(v, h, l);
        const long long o = boff + (long long)yo * R + xo;
        out[o] = h;
        out[plane + o] = l;
    }
}

// row softmax over dist[rows][2048] in place + bf16 split planes
__global__ void softmax_split_kernel(float* __restrict__ dist,
                                     __nv_bfloat16* __restrict__ ds, long long plane)
{
    const long long row = blockIdx.x;
    float* p = dist + row * (long long)KSEQ;
    const int tid = threadIdx.x;

    float4 v0 = ((const float4*)p)[tid];
    float4 v1 = ((const float4*)p)[tid + 256];

    __shared__ float red[8];
    float m = fmaxf(fmaxf(fmaxf(v0.x, v0.y), fmaxf(v0.z, v0.w)),
                    fmaxf(fmaxf(v1.x, v1.y), fmaxf(v1.z, v1.w)));
    #pragma unroll
    for (int o = 16; o > 0; o >>= 1) m = fmaxf(m, __shfl_xor_sync(0xffffffffu, m, o));
    if ((tid & 31) == 0) red[tid >> 5] = m;
    __syncthreads();
    m = red[0];
    #pragma unroll
    for (int i = 1; i < 8; i++) m = fmaxf(m, red[i]);
    __syncthreads();

    v0.x = __expf(v0.x - m); v0.y = __expf(v0.y - m);
    v0.z = __expf(v0.z - m); v0.w = __expf(v0.w - m);
    v1.x = __expf(v1.x - m); v1.y = __expf(v1.y - m);
    v1.z = __expf(v1.z - m); v1.w = __expf(v1.w - m);

    float s = v0.x + v0.y + v0.z + v0.w + v1.x + v1.y + v1.z + v1.w;
    #pragma unroll
    for (int o = 16; o > 0; o >>= 1) s += __shfl_xor_sync(0xffffffffu, s, o);
    if ((tid & 31) == 0) red[tid >> 5] = s;
    __syncthreads();
    float tot = red[0];
    #pragma unroll
    for (int i = 1; i < 8; i++) tot += red[i];

    const float inv = 1.0f / tot;
    v0.x *= inv; v0.y *= inv; v0.z *= inv; v0.w *= inv;
    v1.x *= inv; v1.y *= inv; v1.z *= inv; v1.w *= inv;

    ((float4*)p)[tid]       = v0;
    ((float4*)p)[tid + 256] = v1;

    const long long b0 = row * KSEQ + tid * 4;
    const long long b1 = b0 + 1024;
    __nv_bfloat16 h0, l0, h1, l1;
    splitf(v0.x, h0, l0); splitf(v0.y, h1, l1);
    *(__nv_bfloat162*)(ds + b0)         = __halves2bfloat162(h0, h1);
    *(__nv_bfloat162*)(ds + plane + b0) = __halves2bfloat162(l0, l1);
    splitf(v0.z, h0, l0); splitf(v0.w, h1, l1);
    *(__nv_bfloat162*)(ds + b0 + 2)         = __halves2bfloat162(h0, h1);
    *(__nv_bfloat162*)(ds + plane + b0 + 2) = __halves2bfloat162(l0, l1);
    splitf(v1.x, h0, l0); splitf(v1.y, h1, l1);
    *(__nv_bfloat162*)(ds + b1)         = __halves2bfloat162(h0, h1);
    *(__nv_bfloat162*)(ds + plane + b1) = __halves2bfloat162(l0, l1);
    splitf(v1.z, h0, l0); splitf(v1.w, h1, l1);
    *(__nv_bfloat162*)(ds + b1 + 2)         = __halves2bfloat162(h0, h1);
    *(__nv_bfloat162*)(ds + plane + b1 + 2) = __halves2bfloat162(l0, l1);
}

// ---------------- host side -------------------------------------------------
struct Ctx {
    __nv_bfloat16 *q, *wt, *k, *qw, *vt, *ds;
    cudaStream_t s[3];
    cudaEvent_t ev_root, ev_q, ev_k, ev_v, ev_join[3];
    bool ready;
};
static Ctx& get_ctx()
{
    static Ctx c = {};
    if (!c.ready) {
        cudaGetSymbolAddress((void**)&c.q,  g_qsp);
        cudaGetSymbolAddress((void**)&c.wt, g_wtsp);
        cudaGetSymbolAddress((void**)&c.k,  g_ksp);
        cudaGetSymbolAddress((void**)&c.qw, g_qwsp);
        cudaGetSymbolAddress((void**)&c.vt, g_vtsp);
        cudaGetSymbolAddress((void**)&c.ds, g_dssp);
        for (int i = 0; i < 3; i++)
            cudaStreamCreateWithFlags(&c.s[i], cudaStreamNonBlocking);
        cudaEventCreateWithFlags(&c.ev_root, cudaEventDisableTiming);
        cudaEventCreateWithFlags(&c.ev_q,    cudaEventDisableTiming);
        cudaEventCreateWithFlags(&c.ev_k,    cudaEventDisableTiming);
        cudaEventCreateWithFlags(&c.ev_v,    cudaEventDisableTiming);
        for (int i = 0; i < 3; i++)
            cudaEventCreateWithFlags(&c.ev_join[i], cudaEventDisableTiming);
        cudaFuncSetAttribute(mma_gemm<0>, cudaFuncAttributeMaxDynamicSharedMemorySize, SMEM_DYN);
        cudaFuncSetAttribute(mma_gemm<1>, cudaFuncAttributeMaxDynamicSharedMemorySize, SMEM_DYN);
        cudaFuncSetAttribute(mma_gemm<2>, cudaFuncAttributeMaxDynamicSharedMemorySize, SMEM_DYN);
        c.ready = true;
    }
    return c;
}

extern "C" void kernel_launch(void* const* d_in, const int* in_sizes, int n_in,
                              void* d_out, int out_size)
{
    const float* query = (const float*)d_in[0];
    const float* key   = (const float*)d_in[1];
    const float* value = (const float*)d_in[2];
    const int*   mask  = (const int*)d_in[3];
    const float* W     = (const float*)d_in[4];

    float* ctx  = (float*)d_out;                               // [B,Q,D]
    float* dist = ctx + (long long)BB * QQ * DIM;              // [B,Q,K]

    Ctx& C = get_ctx();
    const float scale = 0.044194173824159216f;                 // 1/sqrt(512)

    const long long PQ = (long long)16384 * 512;
    const long long PV = (long long)4096 * 2048;
    const long long PD = (long long)16384 * 2048;
    const long long PW = (long long)512 * 512;

    cudaStream_t s0 = 0;
    cudaStream_t strm[4] = { s0, C.s[0], C.s[1], C.s[2] };

    // fork side streams from capture origin
    cudaEventRecord(C.ev_root, s0);
    for (int i = 0; i < 3; i++) cudaStreamWaitEvent(C.s[i], C.ev_root, 0);

    // splits in parallel
    split_kernel<<<8192, 256, 0, s0>>>(query, C.q, PQ);
    tsplit_kernel<<<dim3(16, 16, 1), dim3(32, 8), 0, s0>>>(W, C.wt, 512, 512, PW);
    cudaEventRecord(C.ev_q, s0);
    split_kernel<<<8192, 256, 0, C.s[0]>>>(key, C.k, PQ);
    cudaEventRecord(C.ev_k, C.s[0]);
    tsplit_kernel<<<dim3(16, 64, 8), dim3(32, 8), 0, C.s[1]>>>(value, C.vt, 2048, 512, PV);
    cudaEventRecord(C.ev_v, C.s[1]);

    // every batch stream needs q/W, key, value splits
    for (int i = 0; i < 4; i++) {
        cudaStreamWaitEvent(strm[i], C.ev_q, 0);
        cudaStreamWaitEvent(strm[i], C.ev_k, 0);
        cudaStreamWaitEvent(strm[i], C.ev_v, 0);
    }

    // per-batch pipelines, round-robin over 4 streams
    for (int b = 0; b < BB; b++) {
        cudaStream_t st = strm[b & 3];
        const long long ro = (long long)b * QQ;                // row offset

        // GEMM1: qW_b = q_b @ (W^T)^T   (2048x512, K=512)
        mma_gemm<0><<<dim3(4, 16), 256, SMEM_DYN, st>>>(
            C.q + ro * 512, PQ, 512, C.wt, PW, 512, 16,
            nullptr, C.qw + ro * 512, PQ, nullptr, 0.f, 512);

        // GEMM2: scores_b = qW_b @ key_b^T, mask+scale  (2048x2048, K=512)
        mma_gemm<1><<<dim3(16, 16), 256, SMEM_DYN, st>>>(
            C.qw + ro * 512, PQ, 512, C.k + ro * 512, PQ, 512, 16,
            dist + ro * KSEQ, nullptr, 0, mask + (long long)b * KSEQ, scale, 2048);

        // softmax_b + bf16 split
        softmax_split_kernel<<<QQ, 256, 0, st>>>(dist + ro * KSEQ, C.ds + ro * KSEQ, PD);

        // GEMM3: ctx_b = dist_b @ (v_b^T)^T  (2048x512, K=2048)
        mma_gemm<2><<<dim3(4, 16), 256, SMEM_DYN, st>>>(
            C.ds + ro * KSEQ, PD, 2048, C.vt + (long long)b * 512 * 2048, PV, 2048, 64,
            ctx + ro * 512, nullptr, 0, nullptr, 0.f, 512);
    }

    // join side streams back into capture origin
    for (int i = 0; i < 3; i++) {
        cudaEventRecord(C.ev_join[i], C.s[i]);
        cudaStreamWaitEvent(s0, C.ev_join[i], 0);
    }
}

// round 6
// speedup vs baseline: 3.8489x; 1.5275x over previous
#include <cuda_runtime.h>
#include <cuda_bf16.h>
#include <cstdint>

#define BB   8
#define QQ   2048
#define KSEQ 2048
#define DIM  512

// ---------------- device scratch ---------------------------------------------
__device__ __align__(1024) __nv_bfloat16 g_qsp [2u*16384u*512u];   // query split
__device__ __align__(1024) __nv_bfloat16 g_wtsp[2u*512u*512u];     // W^T split
__device__ __align__(1024) __nv_bfloat16 g_ksp [2u*16384u*512u];   // key split
__device__ __align__(1024) __nv_bfloat16 g_qwsp[2u*16384u*512u];   // qW split
__device__ __align__(1024) __nv_bfloat16 g_vtsp[2u*4096u*2048u];   // gathered value^T split
__device__ __align__(1024) __nv_bfloat16 g_dssp[2u*16384u*2048u];  // compacted dist split
__device__ __align__(1024) float         g_scf [16384u*2048u];     // compacted scores fp32
__device__ int g_kidx[BB * KSEQ];   // compacted key indices (zero-padded)
__device__ int g_rank[BB * KSEQ];   // rank of each key position among unmasked
__device__ int g_cnt [BB];          // unmasked count per batch
__device__ int g_nch3[BB];          // ceil(cnt/32) K-chunks for GEMM3

__device__ __forceinline__ uint32_t smem_u32(const void* p) {
    uint32_t a;
    asm("{ .reg .u64 t; cvta.to.shared.u64 t, %1; cvt.u32.u64 %0, t; }"
        : "=r"(a) : "l"(p));
    return a;
}
__device__ __forceinline__ void cp16(uint32_t dst, const void* src) {
    asm volatile("cp.async.cg.shared.global [%0], [%1], 16;"
                 :: "r"(dst), "l"(src) : "memory");
}
__device__ __forceinline__ void cp_commit() {
    asm volatile("cp.async.commit_group;" ::: "memory");
}
__device__ __forceinline__ void cp_wait1() {
    asm volatile("cp.async.wait_group 1;" ::: "memory");
}
__device__ __forceinline__ void cp_wait0() {
    asm volatile("cp.async.wait_group 0;" ::: "memory");
}
__device__ __forceinline__ void ldmx4(uint32_t r[4], uint32_t addr) {
    asm volatile("ldmatrix.sync.aligned.m8n8.x4.shared.b16 {%0,%1,%2,%3}, [%4];"
                 : "=r"(r[0]), "=r"(r[1]), "=r"(r[2]), "=r"(r[3]) : "r"(addr));
}
__device__ __forceinline__ void mma16816(float c[4], const uint32_t a[4], const uint32_t* b) {
    asm volatile("mma.sync.aligned.m16n8k16.row.col.f32.bf16.bf16.f32 "
                 "{%0,%1,%2,%3}, {%4,%5,%6,%7}, {%8,%9}, {%0,%1,%2,%3};"
                 : "+f"(c[0]), "+f"(c[1]), "+f"(c[2]), "+f"(c[3])
                 : "r"(a[0]), "r"(a[1]), "r"(a[2]), "r"(a[3]), "r"(b[0]), "r"(b[1]));
}
__device__ __forceinline__ void splitf(float v, __nv_bfloat16& h, __nv_bfloat16& l) {
    h = __float2bfloat16(v);
    l = __float2bfloat16(v - __bfloat162float(h));
}

// ---------------- bf16x3 mma.sync GEMM ---------------------------------------
// C[M,N] = A[M,K] @ B[N,K]^T (row-major, K contiguous), hi/lo planes.
// 128x128 tile, BK=32, 2-stage cp.async, 8 warps, 2 CTAs/SM.
// gidx: optional row-gather for B.  cntp: optional N-bound (early CTA exit).
// nchp: optional device-side K-chunk count.
#define TILEB 10240
#define STGB  (4 * TILEB)
#define SMEM_DYN (2 * STGB)

// EPI: 0 = bf16-split out (qW), 1 = scale fp32 (scores), 2 = fp32 (ctx)
template <int EPI>
__global__ __launch_bounds__(256, 2) void mma_gemm(
    const __nv_bfloat16* __restrict__ A, long long Aplane, int lda,
    const __nv_bfloat16* __restrict__ B, long long Bplane, int ldb,
    int nch_in,
    float* __restrict__ outF,
    __nv_bfloat16* __restrict__ outH, long long hplane,
    float scale, int ldc,
    const int* __restrict__ gidx, const int* __restrict__ cntp,
    const int* __restrict__ nchp)
{
    if (cntp && (int)(blockIdx.x * 128) >= cntp[0]) return;
    const int nch = nchp ? nchp[0] : nch_in;

    extern __shared__ char smem[];
    const uint32_t sb = smem_u32(smem);

    const int tid = threadIdx.x;
    const int lane = tid & 31, wrp = tid >> 5;
    const int wm = (wrp >> 2) * 64, wn = (wrp & 3) * 32;

    const __nv_bfloat16* Ag = A + (long long)(blockIdx.y * 128) * lda;

    const int r0 = tid >> 2, c0 = (tid & 3) * 8;

    // B row sources (gathered once; constant across K-chunks)
    int br0 = blockIdx.x * 128 + r0, br1 = br0 + 64;
    if (gidx) { br0 = gidx[br0]; br1 = gidx[br1]; }
    const __nv_bfloat16* b_src0 = B + (long long)br0 * ldb + c0;
    const __nv_bfloat16* b_src1 = B + (long long)br1 * ldb + c0;

    const int g = lane >> 3, lr = lane & 7;
    const uint32_t aoff = (uint32_t)(wm + (g & 1) * 8 + lr) * 80 + ((g >> 1) * 16);
    const uint32_t boff = (uint32_t)(wn + ((g >> 1) & 1) * 8 + lr) * 80 + ((g & 1) * 16);

    float acc[4][4][4];
    #pragma unroll
    for (int mt = 0; mt < 4; mt++)
        #pragma unroll
        for (int nt = 0; nt < 4; nt++)
            #pragma unroll
            for (int i = 0; i < 4; i++) acc[mt][nt][i] = 0.f;

    auto load_stage = [&](int buf, int k0) {
        const uint32_t st = sb + buf * STGB;
        const uint32_t d0 = (uint32_t)r0 * 80 + (c0 * 2);
        const uint32_t d1 = (uint32_t)(r0 + 64) * 80 + (c0 * 2);
        const __nv_bfloat16* a0 = Ag + (long long)r0 * lda + k0 + c0;
        const __nv_bfloat16* a1 = a0 + (long long)64 * lda;
        cp16(st + d0,             a0);
        cp16(st + TILEB + d0,     a0 + Aplane);
        cp16(st + d1,             a1);
        cp16(st + TILEB + d1,     a1 + Aplane);
        cp16(st + 2 * TILEB + d0, b_src0 + k0);
        cp16(st + 3 * TILEB + d0, b_src0 + k0 + Bplane);
        cp16(st + 2 * TILEB + d1, b_src1 + k0);
        cp16(st + 3 * TILEB + d1, b_src1 + k0 + Bplane);
        cp_commit();
    };

    load_stage(0, 0);
    load_stage(1, 32);

    for (int kt = 0; kt < nch; ++kt) {
        if (kt + 1 < nch) cp_wait1(); else cp_wait0();
        __syncthreads();

        const uint32_t st = sb + (kt & 1) * STGB;
        #pragma unroll
        for (int kk = 0; kk < 2; kk++) {
            uint32_t ah[4][4], al[4][4], bh[2][4], bl[2][4];
            #pragma unroll
            for (int mt = 0; mt < 4; mt++) {
                const uint32_t ad = st + mt * (16 * 80) + kk * 32 + aoff;
                ldmx4(ah[mt], ad);
                ldmx4(al[mt], ad + TILEB);
            }
            #pragma unroll
            for (int nt2 = 0; nt2 < 2; nt2++) {
                const uint32_t bd = st + 2 * TILEB + nt2 * (16 * 80) + kk * 32 + boff;
                ldmx4(bh[nt2], bd);
                ldmx4(bl[nt2], bd + TILEB);
            }
            #pragma unroll
            for (int mt = 0; mt < 4; mt++)
                #pragma unroll
                for (int nt = 0; nt < 4; nt++) {
                    const uint32_t* ph = &bh[nt >> 1][(nt & 1) * 2];
                    const uint32_t* pl = &bl[nt >> 1][(nt & 1) * 2];
                    mma16816(acc[mt][nt], ah[mt], ph);
                    mma16816(acc[mt][nt], al[mt], ph);
                    mma16816(acc[mt][nt], ah[mt], pl);
                }
        }
        __syncthreads();
        if (kt + 2 < nch) load_stage(kt & 1, (kt + 2) * 32);
    }

    // ---- epilogue ----
    const int rbase = blockIdx.y * 128 + wm + (lane >> 2);
    const int cbase = blockIdx.x * 128 + wn + ((lane & 3) << 1);

    #pragma unroll
    for (int mt = 0; mt < 4; mt++) {
        #pragma unroll
        for (int nt = 0; nt < 4; nt++) {
            const int col = cbase + nt * 8;
            #pragma unroll
            for (int h = 0; h < 2; h++) {
                const int row = rbase + mt * 16 + h * 8;
                float v0 = acc[mt][nt][2 * h], v1 = acc[mt][nt][2 * h + 1];
                if (EPI == 0) {
                    const long long o = (long long)row * ldc + col;
                    __nv_bfloat16 h0, l0, h1, l1;
                    splitf(v0, h0, l0); splitf(v1, h1, l1);
                    *(__nv_bfloat162*)(outH + o)          = __halves2bfloat162(h0, h1);
                    *(__nv_bfloat162*)(outH + hplane + o) = __halves2bfloat162(l0, l1);
                } else if (EPI == 1) {
                    const long long o = (long long)row * ldc + col;
                    *(float2*)(outF + o) = make_float2(v0 * scale, v1 * scale);
                } else {
                    const long long o = (long long)row * ldc + col;
                    *(float2*)(outF + o) = make_float2(v0, v1);
                }
            }
        }
    }
}

// ---------------- mask compaction: indices, ranks, counts --------------------
__global__ void compact_kernel(const int* __restrict__ mask)
{
    const int b = blockIdx.x;
    const int tid = threadIdx.x;                       // 256 threads, 8 elems each
    const int* mrow = mask + b * KSEQ;
    int* kid = g_kidx + b * KSEQ;
    int* rnk = g_rank + b * KSEQ;

    // zero-pad kidx first
    #pragma unroll
    for (int e = 0; e < 8; e++) kid[tid * 8 + e] = 0;
    __syncthreads();

    int m[8], lsum = 0;
    #pragma unroll
    for (int e = 0; e < 8; e++) { m[e] = mrow[tid * 8 + e]; lsum += (m[e] != 0); }

    // warp inclusive scan of lsum
    int s = lsum;
    #pragma unroll
    for (int o = 1; o < 32; o <<= 1) {
        int n = __shfl_up_sync(0xffffffffu, s, o);
        if ((tid & 31) >= o) s += n;
    }
    __shared__ int wsum[8];
    if ((tid & 31) == 31) wsum[tid >> 5] = s;
    __syncthreads();
    int woff = 0, total = 0;
    #pragma unroll
    for (int w = 0; w < 8; w++) {
        if (w < (tid >> 5)) woff += wsum[w];
        total += wsum[w];
    }
    int running = woff + s - lsum;                      // exclusive prefix

    #pragma unroll
    for (int e = 0; e < 8; e++) {
        const int p = tid * 8 + e;
        if (m[e]) { kid[running] = p; rnk[p] = running; running++; }
        else rnk[p] = 0;
    }
    if (tid == 0) { g_cnt[b] = total; g_nch3[b] = (total + 31) / 32; }
}

// ---------------- elementwise split / gather-transpose -----------------------
__global__ void split_kernel(const float* __restrict__ in, __nv_bfloat16* __restrict__ out,
                             long long plane)
{
    const long long i = ((long long)blockIdx.x * blockDim.x + threadIdx.x) * 4;
    float4 v = *(const float4*)(in + i);
    __nv_bfloat16 h0, l0, h1, l1, h2, l2, h3, l3;
    splitf(v.x, h0, l0); splitf(v.y, h1, l1); splitf(v.z, h2, l2); splitf(v.w, h3, l3);
    *(__nv_bfloat162*)(out + i)             = __halves2bfloat162(h0, h1);
    *(__nv_bfloat162*)(out + i + 2)         = __halves2bfloat162(h2, h3);
    *(__nv_bfloat162*)(out + plane + i)     = __halves2bfloat162(l0, l1);
    *(__nv_bfloat162*)(out + plane + i + 2) = __halves2bfloat162(l2, l3);
}

// transpose [R,C] -> [C,R] per batch with optional row gather, bf16-split out
__global__ void tsplit_kernel(const float* __restrict__ in, __nv_bfloat16* __restrict__ out,
                              int R, int C, long long plane, const int* __restrict__ gidx)
{
    __shared__ float t[32][33];
    const int bz = blockIdx.z;
    const long long boff = (long long)bz * R * C;
    const int x = blockIdx.x * 32 + threadIdx.x;
    #pragma unroll
    for (int i = 0; i < 4; ++i) {
        const int y = blockIdx.y * 32 + threadIdx.y + i * 8;
        const int ys = gidx ? gidx[bz * R + y] : y;
        t[threadIdx.y + i * 8][threadIdx.x] = in[boff + (long long)ys * C + x];
    }
    __syncthreads();
    const int xo = blockIdx.y * 32 + threadIdx.x;
    #pragma unroll
    for (int i = 0; i < 4; ++i) {
        const int yo = blockIdx.x * 32 + threadIdx.y + i * 8;
        const float v = t[threadIdx.x][threadIdx.y + i * 8];
        __nv_bfloat16 h, l; splitf(v, h, l);
        const long long o = boff + (long long)yo * R + xo;
        out[o] = h;
        out[plane + o] = l;
    }
}

// ---------------- compacted softmax + scatter to full dist -------------------
// sc:   compacted scores [2048 rows][2048] (only j<cnt valid)
// dist: full fp32 output rows
// ds:   compacted bf16 split planes (zero beyond cnt)
__global__ void softmax_scatter_kernel(const float* __restrict__ sc,
                                       float* __restrict__ dist,
                                       __nv_bfloat16* __restrict__ ds, long long plane,
                                       const int* __restrict__ mask,
                                       const int* __restrict__ rank,
                                       const int* __restrict__ cntp)
{
    const long long row = blockIdx.x;
    const int tid = threadIdx.x;
    const int cn = cntp[0];
    const float* p = sc + row * (long long)KSEQ;

    __shared__ float sm[2048];
    __shared__ float red[8];

    const int j0 = tid * 4, j1 = j0 + 1024;
    float4 v0 = ((const float4*)p)[tid];
    float4 v1 = ((const float4*)p)[tid + 256];

    const float NEG = -1e30f;
    float m = NEG;
    m = fmaxf(m, (j0 + 0 < cn) ? v0.x : NEG);
    m = fmaxf(m, (j0 + 1 < cn) ? v0.y : NEG);
    m = fmaxf(m, (j0 + 2 < cn) ? v0.z : NEG);
    m = fmaxf(m, (j0 + 3 < cn) ? v0.w : NEG);
    m = fmaxf(m, (j1 + 0 < cn) ? v1.x : NEG);
    m = fmaxf(m, (j1 + 1 < cn) ? v1.y : NEG);
    m = fmaxf(m, (j1 + 2 < cn) ? v1.z : NEG);
    m = fmaxf(m, (j1 + 3 < cn) ? v1.w : NEG);
    #pragma unroll
    for (int o = 16; o > 0; o >>= 1) m = fmaxf(m, __shfl_xor_sync(0xffffffffu, m, o));
    if ((tid & 31) == 0) red[tid >> 5] = m;
    __syncthreads();
    m = red[0];
    #pragma unroll
    for (int i = 1; i < 8; i++) m = fmaxf(m, red[i]);
    __syncthreads();

    float e00 = (j0 + 0 < cn) ? __expf(v0.x - m) : 0.f;
    float e01 = (j0 + 1 < cn) ? __expf(v0.y - m) : 0.f;
    float e02 = (j0 + 2 < cn) ? __expf(v0.z - m) : 0.f;
    float e03 = (j0 + 3 < cn) ? __expf(v0.w - m) : 0.f;
    float e10 = (j1 + 0 < cn) ? __expf(v1.x - m) : 0.f;
    float e11 = (j1 + 1 < cn) ? __expf(v1.y - m) : 0.f;
    float e12 = (j1 + 2 < cn) ? __expf(v1.z - m) : 0.f;
    float e13 = (j1 + 3 < cn) ? __expf(v1.w - m) : 0.f;

    float s = e00 + e01 + e02 + e03 + e10 + e11 + e12 + e13;
    #pragma unroll
    for (int o = 16; o > 0; o >>= 1) s += __shfl_xor_sync(0xffffffffu, s, o);
    if ((tid & 31) == 0) red[tid >> 5] = s;
    __syncthreads();
    float tot = red[0];
    #pragma unroll
    for (int i = 1; i < 8; i++) tot += red[i];
    const float inv = 1.0f / tot;

    e00 *= inv; e01 *= inv; e02 *= inv; e03 *= inv;
    e10 *= inv; e11 *= inv; e12 *= inv; e13 *= inv;

    *(float4*)&sm[j0] = make_float4(e00, e01, e02, e03);
    *(float4*)&sm[j1] = make_float4(e10, e11, e12, e13);

    // compacted bf16 split planes (zeros beyond cnt come for free: e==0)
    const long long b0 = row * (long long)KSEQ + j0;
    const long long b1 = row * (long long)KSEQ + j1;
    __nv_bfloat16 h0, l0, h1, l1;
    splitf(e00, h0, l0); splitf(e01, h1, l1);
    *(__nv_bfloat162*)(ds + b0)         = __halves2bfloat162(h0, h1);
    *(__nv_bfloat162*)(ds + plane + b0) = __halves2bfloat162(l0, l1);
    splitf(e02, h0, l0); splitf(e03, h1, l1);
    *(__nv_bfloat162*)(ds + b0 + 2)         = __halves2bfloat162(h0, h1);
    *(__nv_bfloat162*)(ds + plane + b0 + 2) = __halves2bfloat162(l0, l1);
    splitf(e10, h0, l0); splitf(e11, h1, l1);
    *(__nv_bfloat162*)(ds + b1)         = __halves2bfloat162(h0, h1);
    *(__nv_bfloat162*)(ds + plane + b1) = __halves2bfloat162(l0, l1);
    splitf(e12, h0, l0); splitf(e13, h1, l1);
    *(__nv_bfloat162*)(ds + b1 + 2)         = __halves2bfloat162(h0, h1);
    *(__nv_bfloat162*)(ds + plane + b1 + 2) = __halves2bfloat162(l0, l1);

    __syncthreads();

    // scatter to full dist row: out[p] = mask[p] ? sm[rank[p]] : 0
    float* drow = dist + row * (long long)KSEQ;
    #pragma unroll
    for (int h = 0; h < 2; h++) {
        const int idx = tid + h * 256;
        int4 mk = ((const int4*)mask)[idx];
        int4 rk = ((const int4*)rank)[idx];
        float4 o;
        o.x = mk.x ? sm[rk.x] : 0.f;
        o.y = mk.y ? sm[rk.y] : 0.f;
        o.z = mk.z ? sm[rk.z] : 0.f;
        o.w = mk.w ? sm[rk.w] : 0.f;
        ((float4*)drow)[idx] = o;
    }
}

// ---------------- host side --------------------------------------------------
struct Ctx {
    __nv_bfloat16 *q, *wt, *k, *qw, *vt, *ds;
    float* scf;
    int *kidx, *rank, *cnt, *nch3;
    cudaStream_t s[3];
    cudaEvent_t ev_root, ev_c, ev_q, ev_k, ev_v, ev_join[3];
    bool ready;
};
static Ctx& get_ctx()
{
    static Ctx c = {};
    if (!c.ready) {
        cudaGetSymbolAddress((void**)&c.q,    g_qsp);
        cudaGetSymbolAddress((void**)&c.wt,   g_wtsp);
        cudaGetSymbolAddress((void**)&c.k,    g_ksp);
        cudaGetSymbolAddress((void**)&c.qw,   g_qwsp);
        cudaGetSymbolAddress((void**)&c.vt,   g_vtsp);
        cudaGetSymbolAddress((void**)&c.ds,   g_dssp);
        cudaGetSymbolAddress((void**)&c.scf,  g_scf);
        cudaGetSymbolAddress((void**)&c.kidx, g_kidx);
        cudaGetSymbolAddress((void**)&c.rank, g_rank);
        cudaGetSymbolAddress((void**)&c.cnt,  g_cnt);
        cudaGetSymbolAddress((void**)&c.nch3, g_nch3);
        for (int i = 0; i < 3; i++)
            cudaStreamCreateWithFlags(&c.s[i], cudaStreamNonBlocking);
        cudaEventCreateWithFlags(&c.ev_root, cudaEventDisableTiming);
        cudaEventCreateWithFlags(&c.ev_c,    cudaEventDisableTiming);
        cudaEventCreateWithFlags(&c.ev_q,    cudaEventDisableTiming);
        cudaEventCreateWithFlags(&c.ev_k,    cudaEventDisableTiming);
        cudaEventCreateWithFlags(&c.ev_v,    cudaEventDisableTiming);
        for (int i = 0; i < 3; i++)
            cudaEventCreateWithFlags(&c.ev_join[i], cudaEventDisableTiming);
        cudaFuncSetAttribute(mma_gemm<0>, cudaFuncAttributeMaxDynamicSharedMemorySize, SMEM_DYN);
        cudaFuncSetAttribute(mma_gemm<1>, cudaFuncAttributeMaxDynamicSharedMemorySize, SMEM_DYN);
        cudaFuncSetAttribute(mma_gemm<2>, cudaFuncAttributeMaxDynamicSharedMemorySize, SMEM_DYN);
        c.ready = true;
    }
    return c;
}

extern "C" void kernel_launch(void* const* d_in, const int* in_sizes, int n_in,
                              void* d_out, int out_size)
{
    const float* query = (const float*)d_in[0];
    const float* key   = (const float*)d_in[1];
    const float* value = (const float*)d_in[2];
    const int*   mask  = (const int*)d_in[3];
    const float* W     = (const float*)d_in[4];

    float* ctx  = (float*)d_out;                               // [B,Q,D]
    float* dist = ctx + (long long)BB * QQ * DIM;              // [B,Q,K]

    Ctx& C = get_ctx();
    const float scale = 0.044194173824159216f;                 // 1/sqrt(512)

    const long long PQ = (long long)16384 * 512;
    const long long PV = (long long)4096 * 2048;
    const long long PD = (long long)16384 * 2048;
    const long long PW = (long long)512 * 512;

    cudaStream_t s0 = 0;
    cudaStream_t strm[4] = { s0, C.s[0], C.s[1], C.s[2] };

    // fork
    cudaEventRecord(C.ev_root, s0);
    for (int i = 0; i < 3; i++) cudaStreamWaitEvent(C.s[i], C.ev_root, 0);

    // compaction first (tiny), needed by GEMM2 loader, value gather, softmax, GEMM3
    compact_kernel<<<BB, 256, 0, s0>>>(mask);
    cudaEventRecord(C.ev_c, s0);
    for (int i = 0; i < 3; i++) cudaStreamWaitEvent(C.s[i], C.ev_c, 0);

    // splits in parallel
    split_kernel<<<8192, 256, 0, s0>>>(query, C.q, PQ);
    tsplit_kernel<<<dim3(16, 16, 1), dim3(32, 8), 0, s0>>>(W, C.wt, 512, 512, PW, nullptr);
    cudaEventRecord(C.ev_q, s0);
    split_kernel<<<8192, 256, 0, C.s[0]>>>(key, C.k, PQ);
    cudaEventRecord(C.ev_k, C.s[0]);
    // value: gathered (compacted) rows, then transpose+split
    tsplit_kernel<<<dim3(16, 64, 8), dim3(32, 8), 0, C.s[1]>>>(value, C.vt, 2048, 512, PV, C.kidx);
    cudaEventRecord(C.ev_v, C.s[1]);

    for (int i = 0; i < 4; i++) {
        cudaStreamWaitEvent(strm[i], C.ev_q, 0);
        cudaStreamWaitEvent(strm[i], C.ev_k, 0);
        cudaStreamWaitEvent(strm[i], C.ev_v, 0);
    }

    // per-batch pipelines over 4 streams
    for (int b = 0; b < BB; b++) {
        cudaStream_t st = strm[b & 3];
        const long long ro = (long long)b * QQ;

        // GEMM1: qW_b = q_b @ (W^T)^T   (2048x512, K=512)
        mma_gemm<0><<<dim3(4, 16), 256, SMEM_DYN, st>>>(
            C.q + ro * 512, PQ, 512, C.wt, PW, 512, 16,
            nullptr, C.qw + ro * 512, PQ, 0.f, 512,
            nullptr, nullptr, nullptr);

        // GEMM2: compacted scores = qW_b @ gather(key_b)^T * scale
        mma_gemm<1><<<dim3(16, 16), 256, SMEM_DYN, st>>>(
            C.qw + ro * 512, PQ, 512, C.k + ro * 512, PQ, 512, 16,
            C.scf + ro * KSEQ, nullptr, 0, scale, 2048,
            C.kidx + b * KSEQ, C.cnt + b, nullptr);

        // softmax over compacted cols + scatter to full dist + compacted split
        softmax_scatter_kernel<<<QQ, 256, 0, st>>>(
            C.scf + ro * KSEQ, dist + ro * KSEQ, C.ds + ro * KSEQ, PD,
            mask + (long long)b * KSEQ, C.rank + b * KSEQ, C.cnt + b);

        // GEMM3: ctx_b = dist_c @ (v_c^T)^T  (2048x512, K = ~cnt)
        mma_gemm<2><<<dim3(4, 16), 256, SMEM_DYN, st>>>(
            C.ds + ro * KSEQ, PD, 2048, C.vt + (long long)b * 512 * 2048, PV, 2048, 64,
            ctx + ro * 512, nullptr, 0, 0.f, 512,
            nullptr, nullptr, C.nch3 + b);
    }

    // join
    for (int i = 0; i < 3; i++) {
        cudaEventRecord(C.ev_join[i], C.s[i]);
        cudaStreamWaitEvent(s0, C.ev_join[i], 0);
    }
}

// round 7
// speedup vs baseline: 5.2077x; 1.3531x over previous
#include <cuda_runtime.h>
#include <cuda_fp16.h>
#include <cstdint>

#define BB   8
#define QQ   2048
#define KSEQ 2048
#define DIM  512

// ---------------- device scratch (fp16 hi/lo planes) -------------------------
__device__ __align__(1024) __half g_qsp [16384u*512u];       // query hi only
__device__ __align__(1024) __half g_wtsp[2u*512u*512u];      // W^T hi+lo
__device__ __align__(1024) __half g_ksp [2u*16384u*512u];    // key hi+lo
__device__ __align__(1024) __half g_qwsp[16384u*512u];       // qW hi only
__device__ __align__(1024) __half g_vtsp[2u*4096u*2048u];    // gathered value^T hi+lo
__device__ __align__(1024) __half g_dssp[16384u*2048u];      // compacted dist hi only
__device__ __align__(1024) float  g_scf [16384u*2048u];      // compacted scores fp32
__device__ int g_kidx[BB * KSEQ];
__device__ int g_rank[BB * KSEQ];
__device__ int g_cnt [BB];
__device__ int g_nch3[BB];

__device__ __forceinline__ uint32_t smem_u32(const void* p) {
    uint32_t a;
    asm("{ .reg .u64 t; cvta.to.shared.u64 t, %1; cvt.u32.u64 %0, t; }"
        : "=r"(a) : "l"(p));
    return a;
}
__device__ __forceinline__ void cp16(uint32_t dst, const void* src) {
    asm volatile("cp.async.cg.shared.global [%0], [%1], 16;"
                 :: "r"(dst), "l"(src) : "memory");
}
__device__ __forceinline__ void cp_commit() {
    asm volatile("cp.async.commit_group;" ::: "memory");
}
__device__ __forceinline__ void cp_wait1() {
    asm volatile("cp.async.wait_group 1;" ::: "memory");
}
__device__ __forceinline__ void cp_wait0() {
    asm volatile("cp.async.wait_group 0;" ::: "memory");
}
__device__ __forceinline__ void ldmx4(uint32_t r[4], uint32_t addr) {
    asm volatile("ldmatrix.sync.aligned.m8n8.x4.shared.b16 {%0,%1,%2,%3}, [%4];"
                 : "=r"(r[0]), "=r"(r[1]), "=r"(r[2]), "=r"(r[3]) : "r"(addr));
}
__device__ __forceinline__ void mma16816(float c[4], const uint32_t a[4], const uint32_t* b) {
    asm volatile("mma.sync.aligned.m16n8k16.row.col.f32.f16.f16.f32 "
                 "{%0,%1,%2,%3}, {%4,%5,%6,%7}, {%8,%9}, {%0,%1,%2,%3};"
                 : "+f"(c[0]), "+f"(c[1]), "+f"(c[2]), "+f"(c[3])
                 : "r"(a[0]), "r"(a[1]), "r"(a[2]), "r"(a[3]), "r"(b[0]), "r"(b[1]));
}
__device__ __forceinline__ void splitf(float v, __half& h, __half& l) {
    h = __float2half_rn(v);
    l = __float2half_rn(v - __half2float(h));
}

// ---------------- fp16 2-term mma.sync GEMM ----------------------------------
// C = A_h @ (B_h + B_l)^T : A row-major hi plane; B row-major hi+lo planes.
// 128x128 tile, BK=32, 2-stage cp.async, 8 warps, 2 CTAs/SM.
#define TILEB 10240
#define STGB  (3 * TILEB)          // Ah, Bh, Bl
#define SMEM_DYN (2 * STGB)

// EPI: 0 = fp16 hi out (qW), 1 = scale fp32 (scores), 2 = fp32 (ctx)
template <int EPI>
__global__ __launch_bounds__(256, 2) void mma_gemm(
    const __half* __restrict__ A, int lda,
    const __half* __restrict__ B, long long Bplane, int ldb,
    int nch_in,
    float* __restrict__ outF,
    __half* __restrict__ outH,
    float scale, int ldc,
    const int* __restrict__ gidx, const int* __restrict__ cntp,
    const int* __restrict__ nchp)
{
    if (cntp && (int)(blockIdx.x * 128) >= cntp[0]) return;
    const int nch = nchp ? nchp[0] : nch_in;

    extern __shared__ char smem[];
    const uint32_t sb = smem_u32(smem);

    const int tid = threadIdx.x;
    const int lane = tid & 31, wrp = tid >> 5;
    const int wm = (wrp >> 2) * 64, wn = (wrp & 3) * 32;

    const __half* Ag = A + (long long)(blockIdx.y * 128) * lda;

    const int r0 = tid >> 2, c0 = (tid & 3) * 8;

    int br0 = blockIdx.x * 128 + r0, br1 = br0 + 64;
    if (gidx) { br0 = gidx[br0]; br1 = gidx[br1]; }
    const __half* b_src0 = B + (long long)br0 * ldb + c0;
    const __half* b_src1 = B + (long long)br1 * ldb + c0;

    const int g = lane >> 3, lr = lane & 7;
    const uint32_t aoff = (uint32_t)(wm + (g & 1) * 8 + lr) * 80 + ((g >> 1) * 16);
    const uint32_t boff = (uint32_t)(wn + ((g >> 1) & 1) * 8 + lr) * 80 + ((g & 1) * 16);

    float acc[4][4][4];
    #pragma unroll
    for (int mt = 0; mt < 4; mt++)
        #pragma unroll
        for (int nt = 0; nt < 4; nt++)
            #pragma unroll
            for (int i = 0; i < 4; i++) acc[mt][nt][i] = 0.f;

    auto load_stage = [&](int buf, int k0) {
        const uint32_t st = sb + buf * STGB;
        const uint32_t d0 = (uint32_t)r0 * 80 + (c0 * 2);
        const uint32_t d1 = (uint32_t)(r0 + 64) * 80 + (c0 * 2);
        const __half* a0 = Ag + (long long)r0 * lda + k0 + c0;
        const __half* a1 = a0 + (long long)64 * lda;
        cp16(st + d0, a0);
        cp16(st + d1, a1);
        cp16(st + TILEB + d0,     b_src0 + k0);
        cp16(st + 2 * TILEB + d0, b_src0 + k0 + Bplane);
        cp16(st + TILEB + d1,     b_src1 + k0);
        cp16(st + 2 * TILEB + d1, b_src1 + k0 + Bplane);
        cp_commit();
    };

    load_stage(0, 0);
    load_stage(1, 32);

    for (int kt = 0; kt < nch; ++kt) {
        if (kt + 1 < nch) cp_wait1(); else cp_wait0();
        __syncthreads();

        const uint32_t st = sb + (kt & 1) * STGB;
        #pragma unroll
        for (int kk = 0; kk < 2; kk++) {
            uint32_t ah[4][4], bh[2][4], bl[2][4];
            #pragma unroll
            for (int mt = 0; mt < 4; mt++)
                ldmx4(ah[mt], st + mt * (16 * 80) + kk * 32 + aoff);
            #pragma unroll
            for (int nt2 = 0; nt2 < 2; nt2++) {
                const uint32_t bd = st + TILEB + nt2 * (16 * 80) + kk * 32 + boff;
                ldmx4(bh[nt2], bd);
                ldmx4(bl[nt2], bd + TILEB);
            }
            #pragma unroll
            for (int mt = 0; mt < 4; mt++)
                #pragma unroll
                for (int nt = 0; nt < 4; nt++) {
                    const uint32_t* ph = &bh[nt >> 1][(nt & 1) * 2];
                    const uint32_t* pl = &bl[nt >> 1][(nt & 1) * 2];
                    mma16816(acc[mt][nt], ah[mt], ph);
                    mma16816(acc[mt][nt], ah[mt], pl);
                }
        }
        __syncthreads();
        if (kt + 2 < nch) load_stage(kt & 1, (kt + 2) * 32);
    }

    // ---- epilogue ----
    const int rbase = blockIdx.y * 128 + wm + (lane >> 2);
    const int cbase = blockIdx.x * 128 + wn + ((lane & 3) << 1);

    #pragma unroll
    for (int mt = 0; mt < 4; mt++) {
        #pragma unroll
        for (int nt = 0; nt < 4; nt++) {
            const int col = cbase + nt * 8;
            #pragma unroll
            for (int h = 0; h < 2; h++) {
                const int row = rbase + mt * 16 + h * 8;
                float v0 = acc[mt][nt][2 * h], v1 = acc[mt][nt][2 * h + 1];
                const long long o = (long long)row * ldc + col;
                if (EPI == 0) {
                    *(__half2*)(outH + o) =
                        __halves2half2(__float2half_rn(v0), __float2half_rn(v1));
                } else if (EPI == 1) {
                    *(float2*)(outF + o) = make_float2(v0 * scale, v1 * scale);
                } else {
                    *(float2*)(outF + o) = make_float2(v0, v1);
                }
            }
        }
    }
}

// ---------------- mask compaction --------------------------------------------
__global__ void compact_kernel(const int* __restrict__ mask)
{
    const int b = blockIdx.x;
    const int tid = threadIdx.x;
    const int* mrow = mask + b * KSEQ;
    int* kid = g_kidx + b * KSEQ;
    int* rnk = g_rank + b * KSEQ;

    #pragma unroll
    for (int e = 0; e < 8; e++) kid[tid * 8 + e] = 0;
    __syncthreads();

    int m[8], lsum = 0;
    #pragma unroll
    for (int e = 0; e < 8; e++) { m[e] = mrow[tid * 8 + e]; lsum += (m[e] != 0); }

    int s = lsum;
    #pragma unroll
    for (int o = 1; o < 32; o <<= 1) {
        int n = __shfl_up_sync(0xffffffffu, s, o);
        if ((tid & 31) >= o) s += n;
    }
    __shared__ int wsum[8];
    if ((tid & 31) == 31) wsum[tid >> 5] = s;
    __syncthreads();
    int woff = 0, total = 0;
    #pragma unroll
    for (int w = 0; w < 8; w++) {
        if (w < (tid >> 5)) woff += wsum[w];
        total += wsum[w];
    }
    int running = woff + s - lsum;

    #pragma unroll
    for (int e = 0; e < 8; e++) {
        const int p = tid * 8 + e;
        if (m[e]) { kid[running] = p; rnk[p] = running; running++; }
        else rnk[p] = 0;
    }
    if (tid == 0) { g_cnt[b] = total; g_nch3[b] = (total + 31) / 32; }
}

// ---------------- elementwise split / gather-transpose -----------------------
template <int LO>
__global__ void split_kernel(const float* __restrict__ in, __half* __restrict__ out,
                             long long plane)
{
    const long long i = ((long long)blockIdx.x * blockDim.x + threadIdx.x) * 4;
    float4 v = *(const float4*)(in + i);
    __half h0, l0, h1, l1, h2, l2, h3, l3;
    splitf(v.x, h0, l0); splitf(v.y, h1, l1); splitf(v.z, h2, l2); splitf(v.w, h3, l3);
    *(__half2*)(out + i)     = __halves2half2(h0, h1);
    *(__half2*)(out + i + 2) = __halves2half2(h2, h3);
    if (LO) {
        *(__half2*)(out + plane + i)     = __halves2half2(l0, l1);
        *(__half2*)(out + plane + i + 2) = __halves2half2(l2, l3);
    }
}

// transpose [R,C] -> [C,R] per batch with optional row gather, hi+lo out
__global__ void tsplit_kernel(const float* __restrict__ in, __half* __restrict__ out,
                              int R, int C, long long plane, const int* __restrict__ gidx)
{
    __shared__ float t[32][33];
    const int bz = blockIdx.z;
    const long long boff = (long long)bz * R * C;
    const int x = blockIdx.x * 32 + threadIdx.x;
    #pragma unroll
    for (int i = 0; i < 4; ++i) {
        const int y = blockIdx.y * 32 + threadIdx.y + i * 8;
        const int ys = gidx ? gidx[bz * R + y] : y;
        t[threadIdx.y + i * 8][threadIdx.x] = in[boff + (long long)ys * C + x];
    }
    __syncthreads();
    const int xo = blockIdx.y * 32 + threadIdx.x;
    #pragma unroll
    for (int i = 0; i < 4; ++i) {
        const int yo = blockIdx.x * 32 + threadIdx.y + i * 8;
        const float v = t[threadIdx.x][threadIdx.y + i * 8];
        __half h, l; splitf(v, h, l);
        const long long o = boff + (long long)yo * R + xo;
        out[o] = h;
        out[plane + o] = l;
    }
}

// ---------------- compacted softmax + scatter ---------------------------------
__global__ void softmax_scatter_kernel(const float* __restrict__ sc,
                                       float* __restrict__ dist,
                                       __half* __restrict__ ds,
                                       const int* __restrict__ mask,
                                       const int* __restrict__ rank,
                                       const int* __restrict__ cntp)
{
    const long long row = blockIdx.x;
    const int tid = threadIdx.x;
    const int cn = cntp[0];
    const float* p = sc + row * (long long)KSEQ;

    __shared__ float sm[2048];
    __shared__ float red[8];

    const int j0 = tid * 4, j1 = j0 + 1024;
    float4 v0 = ((const float4*)p)[tid];
    float4 v1 = ((const float4*)p)[tid + 256];

    const float NEG = -1e30f;
    float m = NEG;
    m = fmaxf(m, (j0 + 0 < cn) ? v0.x : NEG);
    m = fmaxf(m, (j0 + 1 < cn) ? v0.y : NEG);
    m = fmaxf(m, (j0 + 2 < cn) ? v0.z : NEG);
    m = fmaxf(m, (j0 + 3 < cn) ? v0.w : NEG);
    m = fmaxf(m, (j1 + 0 < cn) ? v1.x : NEG);
    m = fmaxf(m, (j1 + 1 < cn) ? v1.y : NEG);
    m = fmaxf(m, (j1 + 2 < cn) ? v1.z : NEG);
    m = fmaxf(m, (j1 + 3 < cn) ? v1.w : NEG);
    #pragma unroll
    for (int o = 16; o > 0; o >>= 1) m = fmaxf(m, __shfl_xor_sync(0xffffffffu, m, o));
    if ((tid & 31) == 0) red[tid >> 5] = m;
    __syncthreads();
    m = red[0];
    #pragma unroll
    for (int i = 1; i < 8; i++) m = fmaxf(m, red[i]);
    __syncthreads();

    float e00 = (j0 + 0 < cn) ? __expf(v0.x - m) : 0.f;
    float e01 = (j0 + 1 < cn) ? __expf(v0.y - m) : 0.f;
    float e02 = (j0 + 2 < cn) ? __expf(v0.z - m) : 0.f;
    float e03 = (j0 + 3 < cn) ? __expf(v0.w - m) : 0.f;
    float e10 = (j1 + 0 < cn) ? __expf(v1.x - m) : 0.f;
    float e11 = (j1 + 1 < cn) ? __expf(v1.y - m) : 0.f;
    float e12 = (j1 + 2 < cn) ? __expf(v1.z - m) : 0.f;
    float e13 = (j1 + 3 < cn) ? __expf(v1.w - m) : 0.f;

    float s = e00 + e01 + e02 + e03 + e10 + e11 + e12 + e13;
    #pragma unroll
    for (int o = 16; o > 0; o >>= 1) s += __shfl_xor_sync(0xffffffffu, s, o);
    if ((tid & 31) == 0) red[tid >> 5] = s;
    __syncthreads();
    float tot = red[0];
    #pragma unroll
    for (int i = 1; i < 8; i++) tot += red[i];
    const float inv = 1.0f / tot;

    e00 *= inv; e01 *= inv; e02 *= inv; e03 *= inv;
    e10 *= inv; e11 *= inv; e12 *= inv; e13 *= inv;

    *(float4*)&sm[j0] = make_float4(e00, e01, e02, e03);
    *(float4*)&sm[j1] = make_float4(e10, e11, e12, e13);

    // compacted fp16 hi plane (A-side of GEMM3)
    const long long b0 = row * (long long)KSEQ + j0;
    const long long b1 = row * (long long)KSEQ + j1;
    *(__half2*)(ds + b0)     = __halves2half2(__float2half_rn(e00), __float2half_rn(e01));
    *(__half2*)(ds + b0 + 2) = __halves2half2(__float2half_rn(e02), __float2half_rn(e03));
    *(__half2*)(ds + b1)     = __halves2half2(__float2half_rn(e10), __float2half_rn(e11));
    *(__half2*)(ds + b1 + 2) = __halves2half2(__float2half_rn(e12), __float2half_rn(e13));

    __syncthreads();

    float* drow = dist + row * (long long)KSEQ;
    #pragma unroll
    for (int h = 0; h < 2; h++) {
        const int idx = tid + h * 256;
        int4 mk = ((const int4*)mask)[idx];
        int4 rk = ((const int4*)rank)[idx];
        float4 o;
        o.x = mk.x ? sm[rk.x] : 0.f;
        o.y = mk.y ? sm[rk.y] : 0.f;
        o.z = mk.z ? sm[rk.z] : 0.f;
        o.w = mk.w ? sm[rk.w] : 0.f;
        ((float4*)drow)[idx] = o;
    }
}

// ---------------- host side ---------------------------------------------------
struct Ctx {
    __half *q, *wt, *k, *qw, *vt, *ds;
    float* scf;
    int *kidx, *rank, *cnt, *nch3;
    cudaStream_t s[3];
    cudaEvent_t ev_root, ev_c, ev_q, ev_k, ev_v, ev_join[3];
    bool ready;
};
static Ctx& get_ctx()
{
    static Ctx c = {};
    if (!c.ready) {
        cudaGetSymbolAddress((void**)&c.q,    g_qsp);
        cudaGetSymbolAddress((void**)&c.wt,   g_wtsp);
        cudaGetSymbolAddress((void**)&c.k,    g_ksp);
        cudaGetSymbolAddress((void**)&c.qw,   g_qwsp);
        cudaGetSymbolAddress((void**)&c.vt,   g_vtsp);
        cudaGetSymbolAddress((void**)&c.ds,   g_dssp);
        cudaGetSymbolAddress((void**)&c.scf,  g_scf);
        cudaGetSymbolAddress((void**)&c.kidx, g_kidx);
        cudaGetSymbolAddress((void**)&c.rank, g_rank);
        cudaGetSymbolAddress((void**)&c.cnt,  g_cnt);
        cudaGetSymbolAddress((void**)&c.nch3, g_nch3);
        for (int i = 0; i < 3; i++)
            cudaStreamCreateWithFlags(&c.s[i], cudaStreamNonBlocking);
        cudaEventCreateWithFlags(&c.ev_root, cudaEventDisableTiming);
        cudaEventCreateWithFlags(&c.ev_c,    cudaEventDisableTiming);
        cudaEventCreateWithFlags(&c.ev_q,    cudaEventDisableTiming);
        cudaEventCreateWithFlags(&c.ev_k,    cudaEventDisableTiming);
        cudaEventCreateWithFlags(&c.ev_v,    cudaEventDisableTiming);
        for (int i = 0; i < 3; i++)
            cudaEventCreateWithFlags(&c.ev_join[i], cudaEventDisableTiming);
        cudaFuncSetAttribute(mma_gemm<0>, cudaFuncAttributeMaxDynamicSharedMemorySize, SMEM_DYN);
        cudaFuncSetAttribute(mma_gemm<1>, cudaFuncAttributeMaxDynamicSharedMemorySize, SMEM_DYN);
        cudaFuncSetAttribute(mma_gemm<2>, cudaFuncAttributeMaxDynamicSharedMemorySize, SMEM_DYN);
        c.ready = true;
    }
    return c;
}

extern "C" void kernel_launch(void* const* d_in, const int* in_sizes, int n_in,
                              void* d_out, int out_size)
{
    const float* query = (const float*)d_in[0];
    const float* key   = (const float*)d_in[1];
    const float* value = (const float*)d_in[2];
    const int*   mask  = (const int*)d_in[3];
    const float* W     = (const float*)d_in[4];

    float* ctx  = (float*)d_out;                               // [B,Q,D]
    float* dist = ctx + (long long)BB * QQ * DIM;              // [B,Q,K]

    Ctx& C = get_ctx();
    const float scale = 0.044194173824159216f;                 // 1/sqrt(512)

    const long long PQ = (long long)16384 * 512;
    const long long PV = (long long)4096 * 2048;
    const long long PW = (long long)512 * 512;

    cudaStream_t s0 = 0;
    cudaStream_t strm[4] = { s0, C.s[0], C.s[1], C.s[2] };

    cudaEventRecord(C.ev_root, s0);
    for (int i = 0; i < 3; i++) cudaStreamWaitEvent(C.s[i], C.ev_root, 0);

    compact_kernel<<<BB, 256, 0, s0>>>(mask);
    cudaEventRecord(C.ev_c, s0);
    for (int i = 0; i < 3; i++) cudaStreamWaitEvent(C.s[i], C.ev_c, 0);

    split_kernel<0><<<8192, 256, 0, s0>>>(query, C.q, 0);
    tsplit_kernel<<<dim3(16, 16, 1), dim3(32, 8), 0, s0>>>(W, C.wt, 512, 512, PW, nullptr);
    cudaEventRecord(C.ev_q, s0);
    split_kernel<1><<<8192, 256, 0, C.s[0]>>>(key, C.k, PQ);
    cudaEventRecord(C.ev_k, C.s[0]);
    tsplit_kernel<<<dim3(16, 64, 8), dim3(32, 8), 0, C.s[1]>>>(value, C.vt, 2048, 512, PV, C.kidx);
    cudaEventRecord(C.ev_v, C.s[1]);

    for (int i = 0; i < 4; i++) {
        cudaStreamWaitEvent(strm[i], C.ev_q, 0);
        cudaStreamWaitEvent(strm[i], C.ev_k, 0);
        cudaStreamWaitEvent(strm[i], C.ev_v, 0);
    }

    for (int b = 0; b < BB; b++) {
        cudaStream_t st = strm[b & 3];
        const long long ro = (long long)b * QQ;

        // GEMM1: qW_b = q_b @ (W^T)^T  -> fp16 hi
        mma_gemm<0><<<dim3(4, 16), 256, SMEM_DYN, st>>>(
            C.q + ro * 512, 512, C.wt, PW, 512, 16,
            nullptr, C.qw + ro * 512, 0.f, 512,
            nullptr, nullptr, nullptr);

        // GEMM2: compacted scores = qW_b @ gather(key_b)^T * scale
        mma_gemm<1><<<dim3(16, 16), 256, SMEM_DYN, st>>>(
            C.qw + ro * 512, 512, C.k + ro * 512, PQ, 512, 16,
            C.scf + ro * KSEQ, nullptr, scale, 2048,
            C.kidx + b * KSEQ, C.cnt + b, nullptr);

        // softmax + scatter + fp16 hi split
        softmax_scatter_kernel<<<QQ, 256, 0, st>>>(
            C.scf + ro * KSEQ, dist + ro * KSEQ, C.ds + ro * KSEQ,
            mask + (long long)b * KSEQ, C.rank + b * KSEQ, C.cnt + b);

        // GEMM3: ctx_b = dist_c @ (v_c^T)^T
        mma_gemm<2><<<dim3(4, 16), 256, SMEM_DYN, st>>>(
            C.ds + ro * KSEQ, 2048, C.vt + (long long)b * 512 * 2048, PV, 2048, 64,
            ctx + ro * 512, nullptr, 0.f, 512,
            nullptr, nullptr, C.nch3 + b);
    }

    for (int i = 0; i < 3; i++) {
        cudaEventRecord(C.ev_join[i], C.s[i]);
        cudaStreamWaitEvent(s0, C.ev_join[i], 0);
    }
}

// round 9
// speedup vs baseline: 5.2328x; 1.0048x over previous
#include <cuda_runtime.h>
#include <cuda_fp16.h>
#include <cstdint>

#define BB   8
#define QQ   2048
#define KSEQ 2048
#define DIM  512

// ---------------- device scratch (fp16 planes) -------------------------------
__device__ __align__(1024) __half g_qsp [16384u*512u];       // query hi
__device__ __align__(1024) __half g_wsp [2u*512u*512u];      // W row-major hi+lo
__device__ __align__(1024) __half g_ksp [16384u*512u];       // key hi
__device__ __align__(1024) __half g_kwsp[2u*16384u*512u];    // kW = key@W^T (compacted) hi+lo
__device__ __align__(1024) __half g_vtsp[2u*4096u*2048u];    // gathered value^T hi+lo
__device__ __align__(1024) __half g_dssp[16384u*2048u];      // compacted dist hi
__device__ __align__(1024) float  g_scf [16384u*2048u];      // compacted scores fp32
__device__ int g_kidx[BB * KSEQ];
__device__ int g_rank[BB * KSEQ];
__device__ int g_cnt [BB];
__device__ int g_nch3[BB];

__device__ __forceinline__ uint32_t smem_u32(const void* p) {
    uint32_t a;
    asm("{ .reg .u64 t; cvta.to.shared.u64 t, %1; cvt.u32.u64 %0, t; }"
        : "=r"(a) : "l"(p));
    return a;
}
__device__ __forceinline__ void cp16(uint32_t dst, const void* src) {
    asm volatile("cp.async.cg.shared.global [%0], [%1], 16;"
                 :: "r"(dst), "l"(src) : "memory");
}
__device__ __forceinline__ void cp_commit() {
    asm volatile("cp.async.commit_group;" ::: "memory");
}
__device__ __forceinline__ void cp_wait2() {
    asm volatile("cp.async.wait_group 2;" ::: "memory");
}
__device__ __forceinline__ void cp_wait1() {
    asm volatile("cp.async.wait_group 1;" ::: "memory");
}
__device__ __forceinline__ void cp_wait0() {
    asm volatile("cp.async.wait_group 0;" ::: "memory");
}
__device__ __forceinline__ void ldmx4(uint32_t r[4], uint32_t addr) {
    asm volatile("ldmatrix.sync.aligned.m8n8.x4.shared.b16 {%0,%1,%2,%3}, [%4];"
                 : "=r"(r[0]), "=r"(r[1]), "=r"(r[2]), "=r"(r[3]) : "r"(addr));
}
__device__ __forceinline__ void mma16816(float c[4], const uint32_t a[4], const uint32_t* b) {
    asm volatile("mma.sync.aligned.m16n8k16.row.col.f32.f16.f16.f32 "
                 "{%0,%1,%2,%3}, {%4,%5,%6,%7}, {%8,%9}, {%0,%1,%2,%3};"
                 : "+f"(c[0]), "+f"(c[1]), "+f"(c[2]), "+f"(c[3])
                 : "r"(a[0]), "r"(a[1]), "r"(a[2]), "r"(a[3]), "r"(b[0]), "r"(b[1]));
}
__device__ __forceinline__ void splitf(float v, __half& h, __half& l) {
    h = __float2half_rn(v);
    l = __float2half_rn(v - __half2float(h));
}

// ---------------- fp16 2-term mma.sync GEMM ----------------------------------
// C = A_h @ (B_h + B_l)^T.  128x128 tile, BK=32, 3-stage cp.async, 8 warps,
// 2 CTAs/SM.  Optional: A row-gather, M/N early-exit bounds, device K-count.
#define TILEB 10240
#define STGB  (3 * TILEB)          // Ah, Bh, Bl
#define NSTG  3
#define SMEM_DYN (NSTG * STGB)

// EPI: 0 = fp16 hi+lo out (kW), 1 = scale fp32 (scores), 2 = fp32 (ctx)
template <int EPI>
__global__ __launch_bounds__(256, 2) void mma_gemm(
    const __half* __restrict__ A, int lda,
    const __half* __restrict__ B, long long Bplane, int ldb,
    int nch_in,
    float* __restrict__ outF,
    __half* __restrict__ outH, long long hplane,
    float scale, int ldc,
    const int* __restrict__ agidx,
    const int* __restrict__ mcntp, const int* __restrict__ ncntp,
    const int* __restrict__ nchp)
{
    if (mcntp && (int)(blockIdx.y * 128) >= mcntp[0]) return;
    if (ncntp && (int)(blockIdx.x * 128) >= ncntp[0]) return;
    const int nch = nchp ? nchp[0] : nch_in;

    extern __shared__ char smem[];
    const uint32_t sb = smem_u32(smem);

    const int tid = threadIdx.x;
    const int lane = tid & 31, wrp = tid >> 5;
    const int wm = (wrp >> 2) * 64, wn = (wrp & 3) * 32;

    const int r0 = tid >> 2, c0 = (tid & 3) * 8;

    int ar0 = blockIdx.y * 128 + r0, ar1 = ar0 + 64;
    if (agidx) { ar0 = agidx[ar0]; ar1 = agidx[ar1]; }
    const __half* a_src0 = A + (long long)ar0 * lda + c0;
    const __half* a_src1 = A + (long long)ar1 * lda + c0;

    const __half* b_src0 = B + (long long)(blockIdx.x * 128 + r0) * ldb + c0;
    const __half* b_src1 = b_src0 + (long long)64 * ldb;

    const int g = lane >> 3, lr = lane & 7;
    const uint32_t aoff = (uint32_t)(wm + (g & 1) * 8 + lr) * 80 + ((g >> 1) * 16);
    const uint32_t boff = (uint32_t)(wn + ((g >> 1) & 1) * 8 + lr) * 80 + ((g & 1) * 16);

    float acc[4][4][4];
    #pragma unroll
    for (int mt = 0; mt < 4; mt++)
        #pragma unroll
        for (int nt = 0; nt < 4; nt++)
            #pragma unroll
            for (int i = 0; i < 4; i++) acc[mt][nt][i] = 0.f;

    auto load_stage = [&](int buf, int k0) {
        const uint32_t st = sb + buf * STGB;
        const uint32_t d0 = (uint32_t)r0 * 80 + (c0 * 2);
        const uint32_t d1 = (uint32_t)(r0 + 64) * 80 + (c0 * 2);
        cp16(st + d0, a_src0 + k0);
        cp16(st + d1, a_src1 + k0);
        cp16(st + TILEB + d0,     b_src0 + k0);
        cp16(st + 2 * TILEB + d0, b_src0 + k0 + Bplane);
        cp16(st + TILEB + d1,     b_src1 + k0);
        cp16(st + 2 * TILEB + d1, b_src1 + k0 + Bplane);
        cp_commit();
    };

    load_stage(0, 0);
    load_stage(1, 32);
    load_stage(2, 64);

    for (int kt = 0; kt < nch; ++kt) {
        const int rem = nch - 1 - kt;
        if (rem >= 2) cp_wait2();
        else if (rem == 1) cp_wait1();
        else cp_wait0();
        __syncthreads();

        const uint32_t st = sb + (kt % NSTG) * STGB;
        #pragma unroll
        for (int kk = 0; kk < 2; kk++) {
            uint32_t ah[4][4], bh[2][4], bl[2][4];
            #pragma unroll
            for (int mt = 0; mt < 4; mt++)
                ldmx4(ah[mt], st + mt * (16 * 80) + kk * 32 + aoff);
            #pragma unroll
            for (int nt2 = 0; nt2 < 2; nt2++) {
                const uint32_t bd = st + TILEB + nt2 * (16 * 80) + kk * 32 + boff;
                ldmx4(bh[nt2], bd);
                ldmx4(bl[nt2], bd + TILEB);
            }
            #pragma unroll
            for (int mt = 0; mt < 4; mt++)
                #pragma unroll
                for (int nt = 0; nt < 4; nt++) {
                    const uint32_t* ph = &bh[nt >> 1][(nt & 1) * 2];
                    const uint32_t* pl = &bl[nt >> 1][(nt & 1) * 2];
                    mma16816(acc[mt][nt], ah[mt], ph);
                    mma16816(acc[mt][nt], ah[mt], pl);
                }
        }
        __syncthreads();
        if (kt + 3 < nch) load_stage(kt % NSTG, (kt + 3) * 32);
    }

    // ---- epilogue ----
    const int rbase = blockIdx.y * 128 + wm + (lane >> 2);
    const int cbase = blockIdx.x * 128 + wn + ((lane & 3) << 1);

    #pragma unroll
    for (int mt = 0; mt < 4; mt++) {
        #pragma unroll
        for (int nt = 0; nt < 4; nt++) {
            const int col = cbase + nt * 8;
            #pragma unroll
            for (int h = 0; h < 2; h++) {
                const int row = rbase + mt * 16 + h * 8;
                float v0 = acc[mt][nt][2 * h], v1 = acc[mt][nt][2 * h + 1];
                const long long o = (long long)row * ldc + col;
                if (EPI == 0) {
                    __half h0, l0, h1, l1;
                    splitf(v0, h0, l0); splitf(v1, h1, l1);
                    *(__half2*)(outH + o)          = __halves2half2(h0, h1);
                    *(__half2*)(outH + hplane + o) = __halves2half2(l0, l1);
                } else if (EPI == 1) {
                    *(float2*)(outF + o) = make_float2(v0 * scale, v1 * scale);
                } else {
                    *(float2*)(outF + o) = make_float2(v0, v1);
                }
            }
        }
    }
}

// ---------------- mask compaction --------------------------------------------
__global__ void compact_kernel(const int* __restrict__ mask)
{
    const int b = blockIdx.x;
    const int tid = threadIdx.x;
    const int* mrow = mask + b * KSEQ;
    int* kid = g_kidx + b * KSEQ;
    int* rnk = g_rank + b * KSEQ;

    #pragma unroll
    for (int e = 0; e < 8; e++) kid[tid * 8 + e] = 0;
    __syncthreads();

    int m[8], lsum = 0;
    #pragma unroll
    for (int e = 0; e < 8; e++) { m[e] = mrow[tid * 8 + e]; lsum += (m[e] != 0); }

    int s = lsum;
    #pragma unroll
    for (int o = 1; o < 32; o <<= 1) {
        int n = __shfl_up_sync(0xffffffffu, s, o);
        if ((tid & 31) >= o) s += n;
    }
    __shared__ int wsum[8];
    if ((tid & 31) == 31) wsum[tid >> 5] = s;
    __syncthreads();
    int woff = 0, total = 0;
    #pragma unroll
    for (int w = 0; w < 8; w++) {
        if (w < (tid >> 5)) woff += wsum[w];
        total += wsum[w];
    }
    int running = woff + s - lsum;

    #pragma unroll
    for (int e = 0; e < 8; e++) {
        const int p = tid * 8 + e;
        if (m[e]) { kid[running] = p; rnk[p] = running; running++; }
        else rnk[p] = 0;
    }
    if (tid == 0) { g_cnt[b] = total; g_nch3[b] = (total + 31) / 32; }
}

// ---------------- elementwise split / gather-transpose -----------------------
template <int LO>
__global__ void split_kernel(const float* __restrict__ in, __half* __restrict__ out,
                             long long plane)
{
    const long long i = ((long long)blockIdx.x * blockDim.x + threadIdx.x) * 4;
    float4 v = *(const float4*)(in + i);
    __half h0, l0, h1, l1, h2, l2, h3, l3;
    splitf(v.x, h0, l0); splitf(v.y, h1, l1); splitf(v.z, h2, l2); splitf(v.w, h3, l3);
    *(__half2*)(out + i)     = __halves2half2(h0, h1);
    *(__half2*)(out + i + 2) = __halves2half2(h2, h3);
    if (LO) {
        *(__half2*)(out + plane + i)     = __halves2half2(l0, l1);
        *(__half2*)(out + plane + i + 2) = __halves2half2(l2, l3);
    }
}

__global__ void tsplit_kernel(const float* __restrict__ in, __half* __restrict__ out,
                              int R, int C, long long plane, const int* __restrict__ gidx)
{
    __shared__ float t[32][33];
    const int bz = blockIdx.z;
    const long long boff = (long long)bz * R * C;
    const int x = blockIdx.x * 32 + threadIdx.x;
    #pragma unroll
    for (int i = 0; i < 4; ++i) {
        const int y = blockIdx.y * 32 + threadIdx.y + i * 8;
        const int ys = gidx ? gidx[bz * R + y] : y;
        t[threadIdx.y + i * 8][threadIdx.x] = in[boff + (long long)ys * C + x];
    }
    __syncthreads();
    const int xo = blockIdx.y * 32 + threadIdx.x;
    #pragma unroll
    for (int i = 0; i < 4; ++i) {
        const int yo = blockIdx.x * 32 + threadIdx.y + i * 8;
        const float v = t[threadIdx.x][threadIdx.y + i * 8];
        __half h, l; splitf(v, h, l);
        const long long o = boff + (long long)yo * R + xo;
        out[o] = h;
        out[plane + o] = l;
    }
}

// ---------------- compacted softmax + scatter ---------------------------------
__global__ void softmax_scatter_kernel(const float* __restrict__ sc,
                                       float* __restrict__ dist,
                                       __half* __restrict__ ds,
                                       const int* __restrict__ mask,
                                       const int* __restrict__ rank,
                                       const int* __restrict__ cntp)
{
    const long long row = blockIdx.x;
    const int tid = threadIdx.x;
    const int cn = cntp[0];
    const float* p = sc + row * (long long)KSEQ;

    __shared__ float sm[2048];
    __shared__ float red[8];

    const int j0 = tid * 4, j1 = j0 + 1024;
    float4 v0 = ((const float4*)p)[tid];
    float4 v1 = ((const float4*)p)[tid + 256];

    const float NEG = -1e30f;
    float m = NEG;
    m = fmaxf(m, (j0 + 0 < cn) ? v0.x : NEG);
    m = fmaxf(m, (j0 + 1 < cn) ? v0.y : NEG);
    m = fmaxf(m, (j0 + 2 < cn) ? v0.z : NEG);
    m = fmaxf(m, (j0 + 3 < cn) ? v0.w : NEG);
    m = fmaxf(m, (j1 + 0 < cn) ? v1.x : NEG);
    m = fmaxf(m, (j1 + 1 < cn) ? v1.y : NEG);
    m = fmaxf(m, (j1 + 2 < cn) ? v1.z : NEG);
    m = fmaxf(m, (j1 + 3 < cn) ? v1.w : NEG);
    #pragma unroll
    for (int o = 16; o > 0; o >>= 1) m = fmaxf(m, __shfl_xor_sync(0xffffffffu, m, o));
    if ((tid & 31) == 0) red[tid >> 5] = m;
    __syncthreads();
    m = red[0];
    #pragma unroll
    for (int i = 1; i < 8; i++) m = fmaxf(m, red[i]);
    __syncthreads();

    float e00 = (j0 + 0 < cn) ? __expf(v0.x - m) : 0.f;
    float e01 = (j0 + 1 < cn) ? __expf(v0.y - m) : 0.f;
    float e02 = (j0 + 2 < cn) ? __expf(v0.z - m) : 0.f;
    float e03 = (j0 + 3 < cn) ? __expf(v0.w - m) : 0.f;
    float e10 = (j1 + 0 < cn) ? __expf(v1.x - m) : 0.f;
    float e11 = (j1 + 1 < cn) ? __expf(v1.y - m) : 0.f;
    float e12 = (j1 + 2 < cn) ? __expf(v1.z - m) : 0.f;
    float e13 = (j1 + 3 < cn) ? __expf(v1.w - m) : 0.f;

    float s = e00 + e01 + e02 + e03 + e10 + e11 + e12 + e13;
    #pragma unroll
    for (int o = 16; o > 0; o >>= 1) s += __shfl_xor_sync(0xffffffffu, s, o);
    if ((tid & 31) == 0) red[tid >> 5] = s;
    __syncthreads();
    float tot = red[0];
    #pragma unroll
    for (int i = 1; i < 8; i++) tot += red[i];
    const float inv = 1.0f / tot;

    e00 *= inv; e01 *= inv; e02 *= inv; e03 *= inv;
    e10 *= inv; e11 *= inv; e12 *= inv; e13 *= inv;

    *(float4*)&sm[j0] = make_float4(e00, e01, e02, e03);
    *(float4*)&sm[j1] = make_float4(e10, e11, e12, e13);

    const long long b0 = row * (long long)KSEQ + j0;
    const long long b1 = row * (long long)KSEQ + j1;
    *(__half2*)(ds + b0)     = __halves2half2(__float2half_rn(e00), __float2half_rn(e01));
    *(__half2*)(ds + b0 + 2) = __halves2half2(__float2half_rn(e02), __float2half_rn(e03));
    *(__half2*)(ds + b1)     = __halves2half2(__float2half_rn(e10), __float2half_rn(e11));
    *(__half2*)(ds + b1 + 2) = __halves2half2(__float2half_rn(e12), __float2half_rn(e13));

    __syncthreads();

    float* drow = dist + row * (long long)KSEQ;
    #pragma unroll
    for (int h = 0; h < 2; h++) {
        const int idx = tid + h * 256;
        int4 mk = ((const int4*)mask)[idx];
        int4 rk = ((const int4*)rank)[idx];
        float4 o;
        o.x = mk.x ? sm[rk.x] : 0.f;
        o.y = mk.y ? sm[rk.y] : 0.f;
        o.z = mk.z ? sm[rk.z] : 0.f;
        o.w = mk.w ? sm[rk.w] : 0.f;
        ((float4*)drow)[idx] = o;
    }
}

// ---------------- host side ---------------------------------------------------
struct Ctx {
    __half *q, *w, *k, *kw, *vt, *ds;
    float* scf;
    int *kidx, *rank, *cnt, *nch3;
    cudaStream_t s[3];
    cudaEvent_t ev_root, ev_c, ev_q, ev_k, ev_v, ev_join[3];
    bool ready;
};
static Ctx& get_ctx()
{
    static Ctx c = {};
    if (!c.ready) {
        cudaGetSymbolAddress((void**)&c.q,    g_qsp);
        cudaGetSymbolAddress((void**)&c.w,    g_wsp);
        cudaGetSymbolAddress((void**)&c.k,    g_ksp);
        cudaGetSymbolAddress((void**)&c.kw,   g_kwsp);
        cudaGetSymbolAddress((void**)&c.vt,   g_vtsp);
        cudaGetSymbolAddress((void**)&c.ds,   g_dssp);
        cudaGetSymbolAddress((void**)&c.scf,  g_scf);
        cudaGetSymbolAddress((void**)&c.kidx, g_kidx);
        cudaGetSymbolAddress((void**)&c.rank, g_rank);
        cudaGetSymbolAddress((void**)&c.cnt,  g_cnt);
        cudaGetSymbolAddress((void**)&c.nch3, g_nch3);
        for (int i = 0; i < 3; i++)
            cudaStreamCreateWithFlags(&c.s[i], cudaStreamNonBlocking);
        cudaEventCreateWithFlags(&c.ev_root, cudaEventDisableTiming);
        cudaEventCreateWithFlags(&c.ev_c,    cudaEventDisableTiming);
        cudaEventCreateWithFlags(&c.ev_q,    cudaEventDisableTiming);
        cudaEventCreateWithFlags(&c.ev_k,    cudaEventDisableTiming);
        cudaEventCreateWithFlags(&c.ev_v,    cudaEventDisableTiming);
        for (int i = 0; i < 3; i++)
            cudaEventCreateWithFlags(&c.ev_join[i], cudaEventDisableTiming);
        cudaFuncSetAttribute(mma_gemm<0>, cudaFuncAttributeMaxDynamicSharedMemorySize, SMEM_DYN);
        cudaFuncSetAttribute(mma_gemm<1>, cudaFuncAttributeMaxDynamicSharedMemorySize, SMEM_DYN);
        cudaFuncSetAttribute(mma_gemm<2>, cudaFuncAttributeMaxDynamicSharedMemorySize, SMEM_DYN);
        c.ready = true;
    }
    return c;
}

extern "C" void kernel_launch(void* const* d_in, const int* in_sizes, int n_in,
                              void* d_out, int out_size)
{
    const float* query = (const float*)d_in[0];
    const float* key   = (const float*)d_in[1];
    const float* value = (const float*)d_in[2];
    const int*   mask  = (const int*)d_in[3];
    const float* W     = (const float*)d_in[4];

    float* ctx  = (float*)d_out;                               // [B,Q,D]
    float* dist = ctx + (long long)BB * QQ * DIM;              // [B,Q,K]

    Ctx& C = get_ctx();
    const float scale = 0.044194173824159216f;                 // 1/sqrt(512)

    const long long PKW = (long long)16384 * 512;  // kW plane
    const long long PV  = (long long)4096 * 2048;  // vt plane
    const long long PW  = (long long)512 * 512;    // W plane

    cudaStream_t s0 = 0;
    cudaStream_t strm[4] = { s0, C.s[0], C.s[1], C.s[2] };

    cudaEventRecord(C.ev_root, s0);
    for (int i = 0; i < 3; i++) cudaStreamWaitEvent(C.s[i], C.ev_root, 0);

    compact_kernel<<<BB, 256, 0, s0>>>(mask);
    cudaEventRecord(C.ev_c, s0);
    for (int i = 0; i < 3; i++) cudaStreamWaitEvent(C.s[i], C.ev_c, 0);

    // q hi; W row-major hi+lo (B operand of GEMM1: C[m,d]=Σ_e k[m,e]·W[d,e])
    split_kernel<0><<<8192, 256, 0, s0>>>(query, C.q, 0);
    split_kernel<1><<<256, 256, 0, s0>>>(W, C.w, PW);
    cudaEventRecord(C.ev_q, s0);
    split_kernel<0><<<8192, 256, 0, C.s[0]>>>(key, C.k, 0);
    cudaEventRecord(C.ev_k, C.s[0]);
    tsplit_kernel<<<dim3(16, 64, 8), dim3(32, 8), 0, C.s[1]>>>(value, C.vt, 2048, 512, PV, C.kidx);
    cudaEventRecord(C.ev_v, C.s[1]);

    for (int i = 0; i < 4; i++) {
        cudaStreamWaitEvent(strm[i], C.ev_q, 0);
        cudaStreamWaitEvent(strm[i], C.ev_k, 0);
        cudaStreamWaitEvent(strm[i], C.ev_v, 0);
    }

    for (int b = 0; b < BB; b++) {
        cudaStream_t st = strm[b & 3];
        const long long ro = (long long)b * QQ;

        // GEMM1: kW[k,d] = Σ_e gather(k_h)[k,e]·(W_h+W_l)[d,e]  (M = cnt)
        mma_gemm<0><<<dim3(4, 16), 256, SMEM_DYN, st>>>(
            C.k + ro * 512, 512, C.w, PW, 512, 16,
            nullptr, C.kw + (long long)b * QQ * 512, PKW, 0.f, 512,
            C.kidx + b * KSEQ, C.cnt + b, nullptr, nullptr);

        // GEMM2: scores[q,k] = Σ_d q_h[q,d]·(kW_h+kW_l)[k,d] · scale  (N = cnt)
        mma_gemm<1><<<dim3(16, 16), 256, SMEM_DYN, st>>>(
            C.q + ro * 512, 512, C.kw + (long long)b * QQ * 512, PKW, 512, 16,
            C.scf + ro * KSEQ, nullptr, 0, scale, 2048,
            nullptr, nullptr, C.cnt + b, nullptr);

        // softmax + scatter + fp16 hi split
        softmax_scatter_kernel<<<QQ, 256, 0, st>>>(
            C.scf + ro * KSEQ, dist + ro * KSEQ, C.ds + ro * KSEQ,
            mask + (long long)b * KSEQ, C.rank + b * KSEQ, C.cnt + b);

        // GEMM3: ctx_b = dist_c @ (v_c^T hi+lo)^T  (K = ~cnt)
        mma_gemm<2><<<dim3(4, 16), 256, SMEM_DYN, st>>>(
            C.ds + ro * KSEQ, 2048, C.vt + (long long)b * 512 * 2048, PV, 2048, 64,
            ctx + ro * 512, nullptr, 0, 0.f, 512,
            nullptr, nullptr, nullptr, C.nch3 + b);
    }

    for (int i = 0; i < 3; i++) {
        cudaEventRecord(C.ev_join[i], C.s[i]);
        cudaStreamWaitEvent(s0, C.ev_join[i], 0);
    }
}